// round 9
// baseline (speedup 1.0000x reference)
#include <cuda_runtime.h>
#include <math.h>

#define B_   2
#define S_   2048
#define DM_  1024
#define H_   16
#define HD_  64
#define MTOT (B_*S_)

// Scratch (alloc-free rule: __device__ globals)
__device__ float g_Q[MTOT*DM_];
__device__ float g_K[MTOT*DM_];
__device__ float g_V[MTOT*DM_];
__device__ float g_attn[MTOT*DM_];
__device__ float g_x[MTOT*DM_];

__device__ __forceinline__ unsigned f2tf(float f) {
    unsigned u; asm("cvt.rna.tf32.f32 %0, %1;" : "=r"(u) : "f"(f)); return u;
}

__device__ __forceinline__ void mma8(float* d, const unsigned* a, const unsigned* b, const float* c) {
    asm volatile("mma.sync.aligned.m16n8k8.row.col.f32.tf32.tf32.f32 "
        "{%0,%1,%2,%3}, {%4,%5,%6,%7}, {%8,%9}, {%10,%11,%12,%13};"
        : "=f"(d[0]), "=f"(d[1]), "=f"(d[2]), "=f"(d[3])
        : "r"(a[0]), "r"(a[1]), "r"(a[2]), "r"(a[3]),
          "r"(b[0]), "r"(b[1]),
          "f"(c[0]), "f"(c[1]), "f"(c[2]), "f"(c[3]));
}

__device__ __forceinline__ void cpa16(float* smem, const float* gmem) {
    unsigned sa = (unsigned)__cvta_generic_to_shared(smem);
    asm volatile("cp.async.ca.shared.global [%0], [%1], 16;" :: "r"(sa), "l"(gmem));
}
#define CP_COMMIT() asm volatile("cp.async.commit_group;")
#define CP_WAIT(N)  asm volatile("cp.async.wait_group %0;" :: "n"(N))

// ---------------------------------------------------------------------------
// tf32 GEMM core (NT): C[m][n] = sum_k A[m][k]*W[n][k] + bias[n] (+res)
// 128x128 tile, BK=16, cp.async 2-stage. Raw fp32 bits -> mma (HW tf32 trunc).
// 256 threads (8 warps 2x4), warp tile 64x32. smem stride 20 -> conflict-free.
// ---------------------------------------------------------------------------
template<bool ADD_RES>
__device__ __forceinline__
void tgemm_core(const float* __restrict__ A, const float* __restrict__ W,
                const float* __restrict__ bias, const float* __restrict__ res,
                float* __restrict__ C)
{
    __shared__ float As[2][128*20];
    __shared__ float Bs[2][128*20];

    const int tid = threadIdx.x;
    const int warp = tid >> 5, lane = tid & 31;
    const int g = lane >> 2, t = lane & 3;
    const int wm = warp >> 2, wn = warp & 3;
    const int m0 = blockIdx.y * 128, n0 = blockIdx.x * 128;

    const int lr  = tid >> 1;          // 0..127
    const int lcq = (tid & 1) * 8;     // 0 or 8
    const float* Ag = A + (size_t)(m0 + lr) * DM_ + lcq;
    const float* Wg = W + (size_t)(n0 + lr) * DM_ + lcq;

    auto issue = [&](int st, int k0) {
        cpa16(&As[st][lr*20 + lcq],     Ag + k0);
        cpa16(&As[st][lr*20 + lcq + 4], Ag + k0 + 4);
        cpa16(&Bs[st][lr*20 + lcq],     Wg + k0);
        cpa16(&Bs[st][lr*20 + lcq + 4], Wg + k0 + 4);
        CP_COMMIT();
    };

    float acc[4][4][4];
    #pragma unroll
    for (int mt = 0; mt < 4; mt++)
        #pragma unroll
        for (int nt = 0; nt < 4; nt++)
            #pragma unroll
            for (int i = 0; i < 4; i++) acc[mt][nt][i] = 0.f;

    issue(0, 0);
    int st = 0;
    for (int k0 = 0; k0 < DM_; k0 += 16, st ^= 1) {
        CP_WAIT(0);
        __syncthreads();
        if (k0 + 16 < DM_) issue(st ^ 1, k0 + 16);

        #pragma unroll
        for (int ks = 0; ks < 2; ks++) {
            unsigned af[4][4], bf[4][2];
            #pragma unroll
            for (int mt = 0; mt < 4; mt++) {
                int base = (wm*64 + mt*16 + g)*20 + ks*8 + t;
                af[mt][0] = __float_as_uint(As[st][base]);
                af[mt][1] = __float_as_uint(As[st][base + 160]);
                af[mt][2] = __float_as_uint(As[st][base + 4]);
                af[mt][3] = __float_as_uint(As[st][base + 164]);
            }
            #pragma unroll
            for (int nt = 0; nt < 4; nt++) {
                int base = (wn*32 + nt*8 + g)*20 + ks*8 + t;
                bf[nt][0] = __float_as_uint(Bs[st][base]);
                bf[nt][1] = __float_as_uint(Bs[st][base + 4]);
            }
            #pragma unroll
            for (int mt = 0; mt < 4; mt++)
                #pragma unroll
                for (int nt = 0; nt < 4; nt++)
                    mma8(acc[mt][nt], af[mt], bf[nt], acc[mt][nt]);
        }
        __syncthreads();
    }

    #pragma unroll
    for (int mt = 0; mt < 4; mt++) {
        int row = m0 + wm*64 + mt*16 + g;
        #pragma unroll
        for (int nt = 0; nt < 4; nt++) {
            int col = n0 + wn*32 + nt*8 + 2*t;
            float2 bv = *(const float2*)&bias[col];
            float v0 = acc[mt][nt][0] + bv.x, v1 = acc[mt][nt][1] + bv.y;
            float v2 = acc[mt][nt][2] + bv.x, v3 = acc[mt][nt][3] + bv.y;
            if (ADD_RES) {
                float2 r0 = *(const float2*)&res[(size_t)row*DM_ + col];
                float2 r1 = *(const float2*)&res[(size_t)(row+8)*DM_ + col];
                v0 += r0.x; v1 += r0.y; v2 += r1.x; v3 += r1.y;
            }
            *(float2*)&C[(size_t)row*DM_ + col]     = make_float2(v0, v1);
            *(float2*)&C[(size_t)(row+8)*DM_ + col] = make_float2(v2, v3);
        }
    }
}

// Fused Q/K/V projections: blockIdx.z picks which.
__global__ __launch_bounds__(256)
void tgemm_qkv(const float* __restrict__ query, const float* __restrict__ key_,
               const float* __restrict__ value,
               const float* __restrict__ Wq, const float* __restrict__ bq,
               const float* __restrict__ Wk, const float* __restrict__ bk,
               const float* __restrict__ Wv, const float* __restrict__ bv)
{
    int z = blockIdx.z;
    const float* A = (z == 0) ? query : (z == 1 ? key_ : value);
    const float* W = (z == 0) ? Wq : (z == 1 ? Wk : Wv);
    const float* bias = (z == 0) ? bq : (z == 1 ? bk : bv);
    float* C = (z == 0) ? g_Q : (z == 1 ? g_K : g_V);
    tgemm_core<false>(A, W, bias, nullptr, C);
}

__global__ __launch_bounds__(256)
void tgemm_out(const float* __restrict__ Wo, const float* __restrict__ bo,
               const float* __restrict__ res)
{
    tgemm_core<true>((const float*)g_attn, Wo, bo, res, g_x);
}

// ---------------------------------------------------------------------------
// Flash attention, tf32 mma, cp.async double-buffered K/V tiles.
// Block = 256 threads (8 warps), 128 query rows (16/warp). KV tiles of 64 keys.
// Dynamic smem: K[2][64*68] | V[2][64*68] | P/Q[128*68] = 104448 B -> 2 blk/SM.
// One __syncthreads per KV tile; P round-trip is warp-private (syncwarp only).
// ---------------------------------------------------------------------------
#define TSTRIDE 68
#define TSZ     (64*TSTRIDE)

__global__ __launch_bounds__(256, 2)
void flash_tc(const int* __restrict__ mask)
{
    extern __shared__ float sm[];
    float* Ps = sm + 4*TSZ;   // 128 x 68

    const int tid = threadIdx.x;
    const int warp = tid >> 5, lane = tid & 31;
    const int g = lane >> 2, t = lane & 3;
    const int q0 = blockIdx.x * 128;
    const int bh = blockIdx.y, b = bh >> 4, h = bh & 15;
    const int wq = warp * 16;

    const float* qsrc  = g_Q + ((size_t)(b*S_ + q0))*DM_ + h*HD_;
    const float* ksrc0 = g_K + ((size_t)b*S_)*DM_ + h*HD_;
    const float* vsrc0 = g_V + ((size_t)b*S_)*DM_ + h*HD_;

    auto issueKV = [&](int buf, int k0) {
        float* Kd = sm + buf*TSZ;
        float* Vd = sm + 2*TSZ + buf*TSZ;
        const float* kp = ksrc0 + (size_t)k0*DM_;
        const float* vp = vsrc0 + (size_t)k0*DM_;
        #pragma unroll
        for (int i = 0; i < 4; i++) {
            int idx = tid + i*256;
            int r = idx >> 4, c = (idx & 15) * 4;
            cpa16(&Kd[r*TSTRIDE + c], kp + (size_t)r*DM_ + c);
            cpa16(&Vd[r*TSTRIDE + c], vp + (size_t)r*DM_ + c);
        }
        CP_COMMIT();
    };

    // Stage Q (128x64) into Ps, and KV tile 0 into buffer 0.
    {
        int qr = tid >> 4, qc = (tid & 15) * 4;
        #pragma unroll
        for (int j = 0; j < 8; j++) {
            int r = qr + j*16;
            cpa16(&Ps[r*TSTRIDE + qc], qsrc + (size_t)r*DM_ + qc);
        }
        CP_COMMIT();
    }
    issueKV(0, 0);

    CP_WAIT(1);              // Q group complete
    __syncthreads();

    unsigned qf[8][4];
    #pragma unroll
    for (int ks = 0; ks < 8; ks++) {
        int base = (wq + g)*TSTRIDE + ks*8 + t;
        qf[ks][0] = f2tf(Ps[base]                 * 0.125f);
        qf[ks][1] = f2tf(Ps[base + 8*TSTRIDE]     * 0.125f);
        qf[ks][2] = f2tf(Ps[base + 4]             * 0.125f);
        qf[ks][3] = f2tf(Ps[base + 8*TSTRIDE + 4] * 0.125f);
    }

    float o[8][4];
    #pragma unroll
    for (int nt = 0; nt < 8; nt++)
        #pragma unroll
        for (int i = 0; i < 4; i++) o[nt][i] = 0.f;
    float mi[2] = {-1e30f, -1e30f}, li[2] = {0.f, 0.f};

    const int* mrow0 = mask + ((size_t)b*S_ + q0 + wq + g)*S_;
    const int* mrow1 = mrow0 + 8*S_;

    int cur = 0;
    for (int i = 0; i < 32; i++, cur ^= 1) {
        CP_WAIT(0);
        __syncthreads();     // all warps done with old buffers; new tile ready
        if (i + 1 < 32) issueKV(cur ^ 1, (i + 1)*64);

        const float* K = sm + cur*TSZ;
        const float* V = sm + 2*TSZ + cur*TSZ;

        // S = Q K^T
        float s[8][4];
        #pragma unroll
        for (int nt = 0; nt < 8; nt++)
            #pragma unroll
            for (int i2 = 0; i2 < 4; i2++) s[nt][i2] = 0.f;

        #pragma unroll
        for (int ks = 0; ks < 8; ks++) {
            #pragma unroll
            for (int nt = 0; nt < 8; nt++) {
                unsigned bf[2];
                int base = (nt*8 + g)*TSTRIDE + ks*8 + t;
                bf[0] = __float_as_uint(K[base]);
                bf[1] = __float_as_uint(K[base + 4]);
                mma8(s[nt], qf[ks], bf, s[nt]);
            }
        }

        // Mask
        const int k0 = i*64;
        #pragma unroll
        for (int nt = 0; nt < 8; nt++) {
            int c = k0 + nt*8 + 2*t;
            int2 m0v = *(const int2*)&mrow0[c];
            int2 m1v = *(const int2*)&mrow1[c];
            if (m0v.x == 0) s[nt][0] = -1e9f;
            if (m0v.y == 0) s[nt][1] = -1e9f;
            if (m1v.x == 0) s[nt][2] = -1e9f;
            if (m1v.y == 0) s[nt][3] = -1e9f;
        }

        // Online softmax (rows g and g+8 of this warp's 16)
        #pragma unroll
        for (int rr = 0; rr < 2; rr++) {
            float mx = -1e30f;
            #pragma unroll
            for (int nt = 0; nt < 8; nt++)
                mx = fmaxf(mx, fmaxf(s[nt][2*rr], s[nt][2*rr+1]));
            mx = fmaxf(mx, __shfl_xor_sync(0xffffffffu, mx, 1));
            mx = fmaxf(mx, __shfl_xor_sync(0xffffffffu, mx, 2));
            float mnew = fmaxf(mi[rr], mx);
            float alpha = __expf(mi[rr] - mnew);
            float sum = 0.f;
            #pragma unroll
            for (int nt = 0; nt < 8; nt++) {
                s[nt][2*rr]   = __expf(s[nt][2*rr]   - mnew);
                s[nt][2*rr+1] = __expf(s[nt][2*rr+1] - mnew);
                sum += s[nt][2*rr] + s[nt][2*rr+1];
            }
            sum += __shfl_xor_sync(0xffffffffu, sum, 1);
            sum += __shfl_xor_sync(0xffffffffu, sum, 2);
            li[rr] = li[rr]*alpha + sum;
            mi[rr] = mnew;
            #pragma unroll
            for (int nt = 0; nt < 8; nt++) {
                o[nt][2*rr]   *= alpha;
                o[nt][2*rr+1] *= alpha;
            }
        }

        // P -> smem (warp-private rows; raw fp32 bits)
        #pragma unroll
        for (int nt = 0; nt < 8; nt++) {
            int base = (wq + g)*TSTRIDE + nt*8 + 2*t;
            *(float2*)&Ps[base]             = make_float2(s[nt][0], s[nt][1]);
            *(float2*)&Ps[base + 8*TSTRIDE] = make_float2(s[nt][2], s[nt][3]);
        }
        __syncwarp();

        // O += P V
        #pragma unroll
        for (int ks = 0; ks < 8; ks++) {
            unsigned pa[4];
            int base = (wq + g)*TSTRIDE + ks*8 + t;
            pa[0] = __float_as_uint(Ps[base]);
            pa[1] = __float_as_uint(Ps[base + 8*TSTRIDE]);
            pa[2] = __float_as_uint(Ps[base + 4]);
            pa[3] = __float_as_uint(Ps[base + 8*TSTRIDE + 4]);
            #pragma unroll
            for (int nt = 0; nt < 8; nt++) {
                unsigned bf[2];
                bf[0] = __float_as_uint(V[(ks*8 + t)*TSTRIDE + nt*8 + g]);
                bf[1] = __float_as_uint(V[(ks*8 + t + 4)*TSTRIDE + nt*8 + g]);
                mma8(o[nt], pa, bf, o[nt]);
            }
        }
        __syncwarp();   // this warp's P reads done before its next P writes
    }

    // Epilogue
    float inv0 = 1.f / li[0], inv1 = 1.f / li[1];
    float* dst0 = g_attn + ((size_t)(b*S_ + q0 + wq + g))*DM_ + h*HD_;
    float* dst1 = dst0 + (size_t)8*DM_;
    #pragma unroll
    for (int nt = 0; nt < 8; nt++) {
        int c = nt*8 + 2*t;
        *(float2*)&dst0[c] = make_float2(o[nt][0]*inv0, o[nt][1]*inv0);
        *(float2*)&dst1[c] = make_float2(o[nt][2]*inv1, o[nt][3]*inv1);
    }
}

// ---------------------------------------------------------------------------
// LayerNorm: unbiased std (ddof=1), denominator (std + eps). One block per row.
// ---------------------------------------------------------------------------
__global__ __launch_bounds__(256)
void layernorm(const float* __restrict__ gamma, const float* __restrict__ beta,
               float* __restrict__ out)
{
    __shared__ float red[2][8];
    const int row = blockIdx.x;
    const int tid = threadIdx.x;
    const float* xr = g_x + (size_t)row * DM_;
    const int c = tid * 4;

    float4 xv = *(const float4*)(xr + c);
    float sum = xv.x + xv.y + xv.z + xv.w;
    float sq  = xv.x*xv.x + xv.y*xv.y + xv.z*xv.z + xv.w*xv.w;

    #pragma unroll
    for (int off = 16; off > 0; off >>= 1) {
        sum += __shfl_xor_sync(0xffffffffu, sum, off);
        sq  += __shfl_xor_sync(0xffffffffu, sq,  off);
    }
    const int w = tid >> 5, lane = tid & 31;
    if (lane == 0) { red[0][w] = sum; red[1][w] = sq; }
    __syncthreads();
    if (tid == 0) {
        float s = 0.f, q = 0.f;
        #pragma unroll
        for (int i = 0; i < 8; i++) { s += red[0][i]; q += red[1][i]; }
        red[0][0] = s; red[1][0] = q;
    }
    __syncthreads();
    sum = red[0][0]; sq = red[1][0];

    float mean = sum / (float)DM_;
    float var  = (sq - (float)DM_ * mean * mean) / (float)(DM_ - 1);
    var = fmaxf(var, 0.f);
    float inv = 1.f / (sqrtf(var) + 1e-6f);

    float4 g4 = *(const float4*)(gamma + c);
    float4 b4 = *(const float4*)(beta + c);
    float4 ov;
    ov.x = g4.x * (xv.x - mean) * inv + b4.x;
    ov.y = g4.y * (xv.y - mean) * inv + b4.y;
    ov.z = g4.z * (xv.z - mean) * inv + b4.z;
    ov.w = g4.w * (xv.w - mean) * inv + b4.w;
    *(float4*)(out + (size_t)row * DM_ + c) = ov;
}

// ---------------------------------------------------------------------------
extern "C" void kernel_launch(void* const* d_in, const int* in_sizes, int n_in,
                              void* d_out, int out_size)
{
    (void)in_sizes; (void)n_in; (void)out_size;
    const float* query = (const float*)d_in[0];
    const float* key_  = (const float*)d_in[1];
    const float* value = (const float*)d_in[2];
    const int*   mask  = (const int*)  d_in[3];
    const float* Wq = (const float*)d_in[4];
    const float* bq = (const float*)d_in[5];
    const float* Wk = (const float*)d_in[6];
    const float* bk = (const float*)d_in[7];
    const float* Wv = (const float*)d_in[8];
    const float* bv = (const float*)d_in[9];
    const float* Wo = (const float*)d_in[10];
    const float* bo = (const float*)d_in[11];
    const float* gamma = (const float*)d_in[12];
    const float* beta  = (const float*)d_in[13];
    float* out = (float*)d_out;

    const int flash_smem = (4*TSZ + 128*TSTRIDE) * (int)sizeof(float);  // 104448
    cudaFuncSetAttribute(flash_tc, cudaFuncAttributeMaxDynamicSharedMemorySize, flash_smem);

    tgemm_qkv<<<dim3(DM_/128, MTOT/128, 3), 256>>>(query, key_, value,
                                                   Wq, bq, Wk, bk, Wv, bv);

    flash_tc<<<dim3(S_/128, B_*H_), 256, flash_smem>>>(mask);

    tgemm_out<<<dim3(DM_/128, MTOT/128), 256>>>(Wo, bo, query);

    layernorm<<<MTOT, 256>>>(gamma, beta, out);
}

// round 10
// speedup vs baseline: 1.0480x; 1.0480x over previous
#include <cuda_runtime.h>
#include <math.h>

#define B_   2
#define S_   2048
#define DM_  1024
#define H_   16
#define HD_  64
#define MTOT (B_*S_)

// Scratch (alloc-free rule: __device__ globals)
__device__ float g_Q[MTOT*DM_];
__device__ float g_K[MTOT*DM_];
__device__ float g_V[MTOT*DM_];
__device__ float g_attn[MTOT*DM_];
__device__ float g_x[MTOT*DM_];

__device__ __forceinline__ unsigned f2tf(float f) {
    unsigned u; asm("cvt.rna.tf32.f32 %0, %1;" : "=r"(u) : "f"(f)); return u;
}

__device__ __forceinline__ void mma8(float* d, const unsigned* a, const unsigned* b, const float* c) {
    asm volatile("mma.sync.aligned.m16n8k8.row.col.f32.tf32.tf32.f32 "
        "{%0,%1,%2,%3}, {%4,%5,%6,%7}, {%8,%9}, {%10,%11,%12,%13};"
        : "=f"(d[0]), "=f"(d[1]), "=f"(d[2]), "=f"(d[3])
        : "r"(a[0]), "r"(a[1]), "r"(a[2]), "r"(a[3]),
          "r"(b[0]), "r"(b[1]),
          "f"(c[0]), "f"(c[1]), "f"(c[2]), "f"(c[3]));
}

__device__ __forceinline__ void cpa16(float* smem, const float* gmem) {
    unsigned sa = (unsigned)__cvta_generic_to_shared(smem);
    asm volatile("cp.async.ca.shared.global [%0], [%1], 16;" :: "r"(sa), "l"(gmem));
}
#define CP_COMMIT() asm volatile("cp.async.commit_group;")
#define CP_WAIT(N)  asm volatile("cp.async.wait_group %0;" :: "n"(N))

// ---------------------------------------------------------------------------
// tf32 GEMM core (NT): C[m][n] = sum_k A[m][k]*W[n][k] + bias[n] (+res)
// 128x128 tile, BK=32, 2-stage cp.async. Raw fp32 bits -> mma (HW tf32 trunc).
// 256 threads (8 warps 2x4), warp tile 64x32. smem stride 36 -> conflict-free.
// Dynamic smem: 2 stages x (As 128x36 + Bs 128x36) = 73728 B.
// ---------------------------------------------------------------------------
template<bool ADD_RES>
__device__ __forceinline__
void tgemm_core(const float* __restrict__ A, const float* __restrict__ W,
                const float* __restrict__ bias, const float* __restrict__ res,
                float* __restrict__ C)
{
    extern __shared__ float smem[];
    float* As[2] = { smem,            smem + 128*36 };
    float* Bs[2] = { smem + 2*128*36, smem + 3*128*36 };

    const int tid = threadIdx.x;
    const int warp = tid >> 5, lane = tid & 31;
    const int g = lane >> 2, t = lane & 3;
    const int wm = warp >> 2, wn = warp & 3;
    const int m0 = blockIdx.y * 128, n0 = blockIdx.x * 128;

    const int lr = tid >> 1;           // 0..127
    const int lc = (tid & 1) * 16;     // 0 or 16
    const float* Ag = A + (size_t)(m0 + lr) * DM_ + lc;
    const float* Wg = W + (size_t)(n0 + lr) * DM_ + lc;

    auto issue = [&](int st, int k0) {
        #pragma unroll
        for (int j = 0; j < 4; j++) {
            cpa16(&As[st][lr*36 + lc + j*4], Ag + k0 + j*4);
            cpa16(&Bs[st][lr*36 + lc + j*4], Wg + k0 + j*4);
        }
        CP_COMMIT();
    };

    float acc[4][4][4];
    #pragma unroll
    for (int mt = 0; mt < 4; mt++)
        #pragma unroll
        for (int nt = 0; nt < 4; nt++)
            #pragma unroll
            for (int i = 0; i < 4; i++) acc[mt][nt][i] = 0.f;

    issue(0, 0);
    int st = 0;
    for (int k0 = 0; k0 < DM_; k0 += 32, st ^= 1) {
        CP_WAIT(0);
        __syncthreads();   // copies landed AND all warps done with buffer st^1
        if (k0 + 32 < DM_) issue(st ^ 1, k0 + 32);

        #pragma unroll
        for (int ks = 0; ks < 4; ks++) {
            unsigned af[4][4], bf[4][2];
            #pragma unroll
            for (int mt = 0; mt < 4; mt++) {
                int base = (wm*64 + mt*16 + g)*36 + ks*8 + t;
                af[mt][0] = __float_as_uint(As[st][base]);
                af[mt][1] = __float_as_uint(As[st][base + 8*36]);
                af[mt][2] = __float_as_uint(As[st][base + 4]);
                af[mt][3] = __float_as_uint(As[st][base + 8*36 + 4]);
            }
            #pragma unroll
            for (int nt = 0; nt < 4; nt++) {
                int base = (wn*32 + nt*8 + g)*36 + ks*8 + t;
                bf[nt][0] = __float_as_uint(Bs[st][base]);
                bf[nt][1] = __float_as_uint(Bs[st][base + 4]);
            }
            #pragma unroll
            for (int mt = 0; mt < 4; mt++)
                #pragma unroll
                for (int nt = 0; nt < 4; nt++)
                    mma8(acc[mt][nt], af[mt], bf[nt], acc[mt][nt]);
        }
    }

    #pragma unroll
    for (int mt = 0; mt < 4; mt++) {
        int row = m0 + wm*64 + mt*16 + g;
        #pragma unroll
        for (int nt = 0; nt < 4; nt++) {
            int col = n0 + wn*32 + nt*8 + 2*t;
            float2 bv = *(const float2*)&bias[col];
            float v0 = acc[mt][nt][0] + bv.x, v1 = acc[mt][nt][1] + bv.y;
            float v2 = acc[mt][nt][2] + bv.x, v3 = acc[mt][nt][3] + bv.y;
            if (ADD_RES) {
                float2 r0 = *(const float2*)&res[(size_t)row*DM_ + col];
                float2 r1 = *(const float2*)&res[(size_t)(row+8)*DM_ + col];
                v0 += r0.x; v1 += r0.y; v2 += r1.x; v3 += r1.y;
            }
            *(float2*)&C[(size_t)row*DM_ + col]     = make_float2(v0, v1);
            *(float2*)&C[(size_t)(row+8)*DM_ + col] = make_float2(v2, v3);
        }
    }
}

// Fused Q/K/V projections: blockIdx.z picks which.
__global__ __launch_bounds__(256)
void tgemm_qkv(const float* __restrict__ query, const float* __restrict__ key_,
               const float* __restrict__ value,
               const float* __restrict__ Wq, const float* __restrict__ bq,
               const float* __restrict__ Wk, const float* __restrict__ bk,
               const float* __restrict__ Wv, const float* __restrict__ bv)
{
    int z = blockIdx.z;
    const float* A = (z == 0) ? query : (z == 1 ? key_ : value);
    const float* W = (z == 0) ? Wq : (z == 1 ? Wk : Wv);
    const float* bias = (z == 0) ? bq : (z == 1 ? bk : bv);
    float* C = (z == 0) ? g_Q : (z == 1 ? g_K : g_V);
    tgemm_core<false>(A, W, bias, nullptr, C);
}

__global__ __launch_bounds__(256)
void tgemm_out(const float* __restrict__ Wo, const float* __restrict__ bo,
               const float* __restrict__ res)
{
    tgemm_core<true>((const float*)g_attn, Wo, bo, res, g_x);
}

// ---------------------------------------------------------------------------
// Flash attention with tf32 mma.sync — R2-proven version (80 regs, occ 34%).
// Block = 128 threads (4 warps), 64 query rows (16/warp). KV tiles of 64.
// smem: Qs[64][68], KP[64][68] (K tile, reused as P tile), Vs[64][68]. 48KB.
// Q held as register fragments, pre-scaled by 1/sqrt(64).
// ---------------------------------------------------------------------------
__global__ __launch_bounds__(128)
void flash_tc(const int* __restrict__ mask)
{
    __shared__ unsigned KP[64*68];
    __shared__ unsigned Vs[64*68];

    const int tid = threadIdx.x;
    const int warp = tid >> 5, lane = tid & 31;
    const int g = lane >> 2, t = lane & 3;
    const int q0 = blockIdx.x * 64;
    const int bh = blockIdx.y, b = bh >> 4, h = bh & 15;
    const int wq = warp * 16;
    const float scale = 0.125f;

    // Load Q tile into KP, extract fragments, then KP is free for K.
    {
        const float* src = g_Q + ((size_t)(b*S_ + q0))*DM_ + h*HD_;
        #pragma unroll
        for (int i = 0; i < 8; i++) {
            int idx = tid + i*128;
            int r = idx >> 4, c = (idx & 15) << 2;
            float4 v = *(const float4*)(src + (size_t)r*DM_ + c);
            uint4 u; u.x = f2tf(v.x*scale); u.y = f2tf(v.y*scale);
                     u.z = f2tf(v.z*scale); u.w = f2tf(v.w*scale);
            *(uint4*)&KP[r*68 + c] = u;
        }
    }
    __syncthreads();

    unsigned qf[8][4];
    #pragma unroll
    for (int ks = 0; ks < 8; ks++) {
        int base = (wq + g)*68 + ks*8 + t;
        qf[ks][0] = KP[base];
        qf[ks][1] = KP[base + 8*68];
        qf[ks][2] = KP[base + 4];
        qf[ks][3] = KP[base + 8*68 + 4];
    }

    float o[8][4];
    #pragma unroll
    for (int nt = 0; nt < 8; nt++)
        #pragma unroll
        for (int i = 0; i < 4; i++) o[nt][i] = 0.f;
    float mi[2] = {-1e30f, -1e30f}, li[2] = {0.f, 0.f};

    const int* mrow0 = mask + ((size_t)b*S_ + q0 + wq + g)*S_;
    const int* mrow1 = mrow0 + 8*S_;

    for (int k0 = 0; k0 < S_; k0 += 64) {
        __syncthreads();   // previous tile's PV done reading KP/Vs
        {
            const float* ksrc = g_K + ((size_t)(b*S_ + k0))*DM_ + h*HD_;
            const float* vsrc = g_V + ((size_t)(b*S_ + k0))*DM_ + h*HD_;
            #pragma unroll
            for (int i = 0; i < 8; i++) {
                int idx = tid + i*128;
                int r = idx >> 4, c = (idx & 15) << 2;
                float4 kv = *(const float4*)(ksrc + (size_t)r*DM_ + c);
                float4 vv = *(const float4*)(vsrc + (size_t)r*DM_ + c);
                uint4 ku; ku.x = f2tf(kv.x); ku.y = f2tf(kv.y); ku.z = f2tf(kv.z); ku.w = f2tf(kv.w);
                uint4 vu; vu.x = f2tf(vv.x); vu.y = f2tf(vv.y); vu.z = f2tf(vv.z); vu.w = f2tf(vv.w);
                *(uint4*)&KP[r*68 + c] = ku;
                *(uint4*)&Vs[r*68 + c] = vu;
            }
        }
        __syncthreads();

        // S = Q K^T
        float s[8][4];
        #pragma unroll
        for (int nt = 0; nt < 8; nt++)
            #pragma unroll
            for (int i = 0; i < 4; i++) s[nt][i] = 0.f;

        #pragma unroll
        for (int ks = 0; ks < 8; ks++) {
            #pragma unroll
            for (int nt = 0; nt < 8; nt++) {
                unsigned bf[2];
                int base = (nt*8 + g)*68 + ks*8 + t;
                bf[0] = KP[base];
                bf[1] = KP[base + 4];
                mma8(s[nt], qf[ks], bf, s[nt]);
            }
        }

        // Mask
        #pragma unroll
        for (int nt = 0; nt < 8; nt++) {
            int c = k0 + nt*8 + 2*t;
            int2 m0v = *(const int2*)&mrow0[c];
            int2 m1v = *(const int2*)&mrow1[c];
            if (m0v.x == 0) s[nt][0] = -1e9f;
            if (m0v.y == 0) s[nt][1] = -1e9f;
            if (m1v.x == 0) s[nt][2] = -1e9f;
            if (m1v.y == 0) s[nt][3] = -1e9f;
        }

        // Online softmax; row rr=0 -> frag slots 0,1 (row g); rr=1 -> 2,3 (row g+8)
        #pragma unroll
        for (int rr = 0; rr < 2; rr++) {
            float mx = -1e30f;
            #pragma unroll
            for (int nt = 0; nt < 8; nt++)
                mx = fmaxf(mx, fmaxf(s[nt][2*rr], s[nt][2*rr+1]));
            mx = fmaxf(mx, __shfl_xor_sync(0xffffffffu, mx, 1));
            mx = fmaxf(mx, __shfl_xor_sync(0xffffffffu, mx, 2));
            float mnew = fmaxf(mi[rr], mx);
            float alpha = __expf(mi[rr] - mnew);
            float sum = 0.f;
            #pragma unroll
            for (int nt = 0; nt < 8; nt++) {
                s[nt][2*rr]   = __expf(s[nt][2*rr]   - mnew);
                s[nt][2*rr+1] = __expf(s[nt][2*rr+1] - mnew);
                sum += s[nt][2*rr] + s[nt][2*rr+1];
            }
            sum += __shfl_xor_sync(0xffffffffu, sum, 1);
            sum += __shfl_xor_sync(0xffffffffu, sum, 2);
            li[rr] = li[rr]*alpha + sum;
            mi[rr] = mnew;
            #pragma unroll
            for (int nt = 0; nt < 8; nt++) {
                o[nt][2*rr]   *= alpha;
                o[nt][2*rr+1] *= alpha;
            }
        }

        __syncthreads();   // all warps done reading KP as K
        // Write P (raw fp32 bits; mma truncates) into KP: P[q][key], stride 68
        #pragma unroll
        for (int nt = 0; nt < 8; nt++) {
            int base = (wq + g)*68 + nt*8 + 2*t;
            uint2 p0; p0.x = __float_as_uint(s[nt][0]); p0.y = __float_as_uint(s[nt][1]);
            uint2 p1; p1.x = __float_as_uint(s[nt][2]); p1.y = __float_as_uint(s[nt][3]);
            *(uint2*)&KP[base]        = p0;
            *(uint2*)&KP[base + 8*68] = p1;
        }
        __syncthreads();

        // O += P V
        #pragma unroll
        for (int ks = 0; ks < 8; ks++) {
            unsigned pa[4];
            int base = (wq + g)*68 + ks*8 + t;
            pa[0] = KP[base];
            pa[1] = KP[base + 8*68];
            pa[2] = KP[base + 4];
            pa[3] = KP[base + 8*68 + 4];
            #pragma unroll
            for (int nt = 0; nt < 8; nt++) {
                unsigned bf[2];
                bf[0] = Vs[(ks*8 + t)*68 + nt*8 + g];
                bf[1] = Vs[(ks*8 + t + 4)*68 + nt*8 + g];
                mma8(o[nt], pa, bf, o[nt]);
            }
        }
    }

    // Epilogue
    float inv0 = 1.f / li[0], inv1 = 1.f / li[1];
    float* dst0 = g_attn + ((size_t)(b*S_ + q0 + wq + g))*DM_ + h*HD_;
    float* dst1 = dst0 + (size_t)8*DM_;
    #pragma unroll
    for (int nt = 0; nt < 8; nt++) {
        int c = nt*8 + 2*t;
        *(float2*)&dst0[c] = make_float2(o[nt][0]*inv0, o[nt][1]*inv0);
        *(float2*)&dst1[c] = make_float2(o[nt][2]*inv1, o[nt][3]*inv1);
    }
}

// ---------------------------------------------------------------------------
// LayerNorm: unbiased std (ddof=1), denominator (std + eps). One block per row.
// ---------------------------------------------------------------------------
__global__ __launch_bounds__(256)
void layernorm(const float* __restrict__ gamma, const float* __restrict__ beta,
               float* __restrict__ out)
{
    __shared__ float red[2][8];
    const int row = blockIdx.x;
    const int tid = threadIdx.x;
    const float* xr = g_x + (size_t)row * DM_;
    const int c = tid * 4;

    float4 xv = *(const float4*)(xr + c);
    float sum = xv.x + xv.y + xv.z + xv.w;
    float sq  = xv.x*xv.x + xv.y*xv.y + xv.z*xv.z + xv.w*xv.w;

    #pragma unroll
    for (int off = 16; off > 0; off >>= 1) {
        sum += __shfl_xor_sync(0xffffffffu, sum, off);
        sq  += __shfl_xor_sync(0xffffffffu, sq,  off);
    }
    const int w = tid >> 5, lane = tid & 31;
    if (lane == 0) { red[0][w] = sum; red[1][w] = sq; }
    __syncthreads();
    if (tid == 0) {
        float s = 0.f, q = 0.f;
        #pragma unroll
        for (int i = 0; i < 8; i++) { s += red[0][i]; q += red[1][i]; }
        red[0][0] = s; red[1][0] = q;
    }
    __syncthreads();
    sum = red[0][0]; sq = red[1][0];

    float mean = sum / (float)DM_;
    float var  = (sq - (float)DM_ * mean * mean) / (float)(DM_ - 1);
    var = fmaxf(var, 0.f);
    float inv = 1.f / (sqrtf(var) + 1e-6f);

    float4 g4 = *(const float4*)(gamma + c);
    float4 b4 = *(const float4*)(beta + c);
    float4 ov;
    ov.x = g4.x * (xv.x - mean) * inv + b4.x;
    ov.y = g4.y * (xv.y - mean) * inv + b4.y;
    ov.z = g4.z * (xv.z - mean) * inv + b4.z;
    ov.w = g4.w * (xv.w - mean) * inv + b4.w;
    *(float4*)(out + (size_t)row * DM_ + c) = ov;
}

// ---------------------------------------------------------------------------
extern "C" void kernel_launch(void* const* d_in, const int* in_sizes, int n_in,
                              void* d_out, int out_size)
{
    (void)in_sizes; (void)n_in; (void)out_size;
    const float* query = (const float*)d_in[0];
    const float* key_  = (const float*)d_in[1];
    const float* value = (const float*)d_in[2];
    const int*   mask  = (const int*)  d_in[3];
    const float* Wq = (const float*)d_in[4];
    const float* bq = (const float*)d_in[5];
    const float* Wk = (const float*)d_in[6];
    const float* bk = (const float*)d_in[7];
    const float* Wv = (const float*)d_in[8];
    const float* bv = (const float*)d_in[9];
    const float* Wo = (const float*)d_in[10];
    const float* bo = (const float*)d_in[11];
    const float* gamma = (const float*)d_in[12];
    const float* beta  = (const float*)d_in[13];
    float* out = (float*)d_out;

    const int gemm_smem = 4 * 128 * 36 * (int)sizeof(float);  // 73728 B
    cudaFuncSetAttribute(tgemm_qkv, cudaFuncAttributeMaxDynamicSharedMemorySize, gemm_smem);
    cudaFuncSetAttribute(tgemm_out, cudaFuncAttributeMaxDynamicSharedMemorySize, gemm_smem);

    tgemm_qkv<<<dim3(DM_/128, MTOT/128, 3), 256, gemm_smem>>>(query, key_, value,
                                                              Wq, bq, Wk, bk, Wv, bv);

    flash_tc<<<dim3(S_/64, B_*H_), 128>>>(mask);

    tgemm_out<<<dim3(DM_/128, MTOT/128), 256, gemm_smem>>>(Wo, bo, query);

    layernorm<<<MTOT, 256>>>(gamma, beta, out);
}

// round 11
// speedup vs baseline: 1.1036x; 1.0531x over previous
#include <cuda_runtime.h>
#include <math.h>

#define B_   2
#define S_   2048
#define DM_  1024
#define H_   16
#define HD_  64
#define MTOT (B_*S_)

// Scratch (alloc-free rule: __device__ globals)
__device__ float g_Q[MTOT*DM_];
__device__ float g_K[MTOT*DM_];
__device__ float g_V[MTOT*DM_];
__device__ float g_attn[MTOT*DM_];
__device__ float g_x[MTOT*DM_];

__device__ __forceinline__ unsigned f2tf(float f) {
    unsigned u; asm("cvt.rna.tf32.f32 %0, %1;" : "=r"(u) : "f"(f)); return u;
}

__device__ __forceinline__ void mma8(float* d, const unsigned* a, const unsigned* b, const float* c) {
    asm volatile("mma.sync.aligned.m16n8k8.row.col.f32.tf32.tf32.f32 "
        "{%0,%1,%2,%3}, {%4,%5,%6,%7}, {%8,%9}, {%10,%11,%12,%13};"
        : "=f"(d[0]), "=f"(d[1]), "=f"(d[2]), "=f"(d[3])
        : "r"(a[0]), "r"(a[1]), "r"(a[2]), "r"(a[3]),
          "r"(b[0]), "r"(b[1]),
          "f"(c[0]), "f"(c[1]), "f"(c[2]), "f"(c[3]));
}

// ---------------------------------------------------------------------------
// tf32 tensor-core GEMM (NT) — R2-proven body (fastest measured GEMM).
// C[m][n] = sum_k A[m][k]*W[n][k] + bias[n] (+res). 128x128 tile, BK=32,
// 256 threads (8 warps 2x4), warp tile 64x32, static smem stride 36.
// Blocking LDG loads; ptxas pipelines them across the MMA stream.
// ---------------------------------------------------------------------------
template<bool ADD_RES>
__device__ __forceinline__
void tgemm_core(const float* __restrict__ A, const float* __restrict__ W,
                const float* __restrict__ bias, const float* __restrict__ res,
                float* __restrict__ C)
{
    __shared__ unsigned As[128*36];
    __shared__ unsigned Bs[128*36];

    const int tid = threadIdx.x;
    const int warp = tid >> 5, lane = tid & 31;
    const int g = lane >> 2, t = lane & 3;
    const int wm = warp >> 2, wn = warp & 3;       // 2 x 4 warp grid
    const int m0 = blockIdx.y * 128, n0 = blockIdx.x * 128;

    float acc[4][4][4];
    #pragma unroll
    for (int mt = 0; mt < 4; mt++)
        #pragma unroll
        for (int nt = 0; nt < 4; nt++)
            #pragma unroll
            for (int i = 0; i < 4; i++) acc[mt][nt][i] = 0.f;

    for (int k0 = 0; k0 < DM_; k0 += 32) {
        __syncthreads();
        #pragma unroll
        for (int i = 0; i < 4; i++) {
            int idx = tid + i*256;
            int r = idx >> 3, c = (idx & 7) << 2;
            float4 a4 = *(const float4*)(A + (size_t)(m0 + r)*DM_ + k0 + c);
            float4 w4 = *(const float4*)(W + (size_t)(n0 + r)*DM_ + k0 + c);
            uint4 at; at.x = f2tf(a4.x); at.y = f2tf(a4.y); at.z = f2tf(a4.z); at.w = f2tf(a4.w);
            uint4 wt; wt.x = f2tf(w4.x); wt.y = f2tf(w4.y); wt.z = f2tf(w4.z); wt.w = f2tf(w4.w);
            *(uint4*)&As[r*36 + c] = at;
            *(uint4*)&Bs[r*36 + c] = wt;
        }
        __syncthreads();

        #pragma unroll
        for (int ks = 0; ks < 4; ks++) {
            unsigned af[4][4], bf[4][2];
            #pragma unroll
            for (int mt = 0; mt < 4; mt++) {
                int base = (wm*64 + mt*16 + g)*36 + ks*8 + t;
                af[mt][0] = As[base];
                af[mt][1] = As[base + 8*36];
                af[mt][2] = As[base + 4];
                af[mt][3] = As[base + 8*36 + 4];
            }
            #pragma unroll
            for (int nt = 0; nt < 4; nt++) {
                int base = (wn*32 + nt*8 + g)*36 + ks*8 + t;
                bf[nt][0] = Bs[base];
                bf[nt][1] = Bs[base + 4];
            }
            #pragma unroll
            for (int mt = 0; mt < 4; mt++)
                #pragma unroll
                for (int nt = 0; nt < 4; nt++)
                    mma8(acc[mt][nt], af[mt], bf[nt], acc[mt][nt]);
        }
    }

    #pragma unroll
    for (int mt = 0; mt < 4; mt++) {
        int row = m0 + wm*64 + mt*16 + g;
        #pragma unroll
        for (int nt = 0; nt < 4; nt++) {
            int col = n0 + wn*32 + nt*8 + 2*t;
            float2 bv = *(const float2*)&bias[col];
            float v0 = acc[mt][nt][0] + bv.x, v1 = acc[mt][nt][1] + bv.y;
            float v2 = acc[mt][nt][2] + bv.x, v3 = acc[mt][nt][3] + bv.y;
            if (ADD_RES) {
                float2 r0 = *(const float2*)&res[(size_t)row*DM_ + col];
                float2 r1 = *(const float2*)&res[(size_t)(row+8)*DM_ + col];
                v0 += r0.x; v1 += r0.y; v2 += r1.x; v3 += r1.y;
            }
            *(float2*)&C[(size_t)row*DM_ + col]     = make_float2(v0, v1);
            *(float2*)&C[(size_t)(row+8)*DM_ + col] = make_float2(v2, v3);
        }
    }
}

// Fused Q/K/V projections: blockIdx.z picks which.
__global__ __launch_bounds__(256)
void tgemm_qkv(const float* __restrict__ query, const float* __restrict__ key_,
               const float* __restrict__ value,
               const float* __restrict__ Wq, const float* __restrict__ bq,
               const float* __restrict__ Wk, const float* __restrict__ bk,
               const float* __restrict__ Wv, const float* __restrict__ bv)
{
    int z = blockIdx.z;
    const float* A = (z == 0) ? query : (z == 1 ? key_ : value);
    const float* W = (z == 0) ? Wq : (z == 1 ? Wk : Wv);
    const float* bias = (z == 0) ? bq : (z == 1 ? bk : bv);
    float* C = (z == 0) ? g_Q : (z == 1 ? g_K : g_V);
    tgemm_core<false>(A, W, bias, nullptr, C);
}

__global__ __launch_bounds__(256)
void tgemm_out(const float* __restrict__ Wo, const float* __restrict__ bo,
               const float* __restrict__ res)
{
    tgemm_core<true>((const float*)g_attn, Wo, bo, res, g_x);
}

// ---------------------------------------------------------------------------
// Flash attention with tf32 mma.sync — R2 body, two targeted fixes:
//  (1) V smem stride 72 (=8 mod 32): PV B-frag bank = 8t+g, a bijection ->
//      conflict-free (was 2-way conflicted at stride 68).
//  (2) post-P-write barrier relaxed to __syncwarp (P rows are warp-private;
//      cross-warp hazards covered by the surrounding __syncthreads).
// Block = 128 threads (4 warps), 64 query rows. smem ~35.8 KB static.
// ---------------------------------------------------------------------------
#define VST 72

__global__ __launch_bounds__(128)
void flash_tc(const int* __restrict__ mask)
{
    __shared__ unsigned KP[64*68];
    __shared__ unsigned Vs[64*VST];

    const int tid = threadIdx.x;
    const int warp = tid >> 5, lane = tid & 31;
    const int g = lane >> 2, t = lane & 3;
    const int q0 = blockIdx.x * 64;
    const int bh = blockIdx.y, b = bh >> 4, h = bh & 15;
    const int wq = warp * 16;
    const float scale = 0.125f;

    // Load Q tile into KP, extract fragments, then KP is free for K.
    {
        const float* src = g_Q + ((size_t)(b*S_ + q0))*DM_ + h*HD_;
        #pragma unroll
        for (int i = 0; i < 8; i++) {
            int idx = tid + i*128;
            int r = idx >> 4, c = (idx & 15) << 2;
            float4 v = *(const float4*)(src + (size_t)r*DM_ + c);
            uint4 u; u.x = f2tf(v.x*scale); u.y = f2tf(v.y*scale);
                     u.z = f2tf(v.z*scale); u.w = f2tf(v.w*scale);
            *(uint4*)&KP[r*68 + c] = u;
        }
    }
    __syncthreads();

    unsigned qf[8][4];
    #pragma unroll
    for (int ks = 0; ks < 8; ks++) {
        int base = (wq + g)*68 + ks*8 + t;
        qf[ks][0] = KP[base];
        qf[ks][1] = KP[base + 8*68];
        qf[ks][2] = KP[base + 4];
        qf[ks][3] = KP[base + 8*68 + 4];
    }

    float o[8][4];
    #pragma unroll
    for (int nt = 0; nt < 8; nt++)
        #pragma unroll
        for (int i = 0; i < 4; i++) o[nt][i] = 0.f;
    float mi[2] = {-1e30f, -1e30f}, li[2] = {0.f, 0.f};

    const int* mrow0 = mask + ((size_t)b*S_ + q0 + wq + g)*S_;
    const int* mrow1 = mrow0 + 8*S_;

    for (int k0 = 0; k0 < S_; k0 += 64) {
        __syncthreads();   // previous tile's PV done reading KP(P rows)/Vs
        {
            const float* ksrc = g_K + ((size_t)(b*S_ + k0))*DM_ + h*HD_;
            const float* vsrc = g_V + ((size_t)(b*S_ + k0))*DM_ + h*HD_;
            #pragma unroll
            for (int i = 0; i < 8; i++) {
                int idx = tid + i*128;
                int r = idx >> 4, c = (idx & 15) << 2;
                float4 kv = *(const float4*)(ksrc + (size_t)r*DM_ + c);
                float4 vv = *(const float4*)(vsrc + (size_t)r*DM_ + c);
                uint4 ku; ku.x = f2tf(kv.x); ku.y = f2tf(kv.y); ku.z = f2tf(kv.z); ku.w = f2tf(kv.w);
                uint4 vu; vu.x = f2tf(vv.x); vu.y = f2tf(vv.y); vu.z = f2tf(vv.z); vu.w = f2tf(vv.w);
                *(uint4*)&KP[r*68 + c]  = ku;
                *(uint4*)&Vs[r*VST + c] = vu;
            }
        }
        __syncthreads();

        // S = Q K^T
        float s[8][4];
        #pragma unroll
        for (int nt = 0; nt < 8; nt++)
            #pragma unroll
            for (int i = 0; i < 4; i++) s[nt][i] = 0.f;

        #pragma unroll
        for (int ks = 0; ks < 8; ks++) {
            #pragma unroll
            for (int nt = 0; nt < 8; nt++) {
                unsigned bf[2];
                int base = (nt*8 + g)*68 + ks*8 + t;
                bf[0] = KP[base];
                bf[1] = KP[base + 4];
                mma8(s[nt], qf[ks], bf, s[nt]);
            }
        }

        // Mask
        #pragma unroll
        for (int nt = 0; nt < 8; nt++) {
            int c = k0 + nt*8 + 2*t;
            int2 m0v = *(const int2*)&mrow0[c];
            int2 m1v = *(const int2*)&mrow1[c];
            if (m0v.x == 0) s[nt][0] = -1e9f;
            if (m0v.y == 0) s[nt][1] = -1e9f;
            if (m1v.x == 0) s[nt][2] = -1e9f;
            if (m1v.y == 0) s[nt][3] = -1e9f;
        }

        // Online softmax; rr=0 -> frag slots 0,1 (row g); rr=1 -> 2,3 (row g+8)
        #pragma unroll
        for (int rr = 0; rr < 2; rr++) {
            float mx = -1e30f;
            #pragma unroll
            for (int nt = 0; nt < 8; nt++)
                mx = fmaxf(mx, fmaxf(s[nt][2*rr], s[nt][2*rr+1]));
            mx = fmaxf(mx, __shfl_xor_sync(0xffffffffu, mx, 1));
            mx = fmaxf(mx, __shfl_xor_sync(0xffffffffu, mx, 2));
            float mnew = fmaxf(mi[rr], mx);
            float alpha = __expf(mi[rr] - mnew);
            float sum = 0.f;
            #pragma unroll
            for (int nt = 0; nt < 8; nt++) {
                s[nt][2*rr]   = __expf(s[nt][2*rr]   - mnew);
                s[nt][2*rr+1] = __expf(s[nt][2*rr+1] - mnew);
                sum += s[nt][2*rr] + s[nt][2*rr+1];
            }
            sum += __shfl_xor_sync(0xffffffffu, sum, 1);
            sum += __shfl_xor_sync(0xffffffffu, sum, 2);
            li[rr] = li[rr]*alpha + sum;
            mi[rr] = mnew;
            #pragma unroll
            for (int nt = 0; nt < 8; nt++) {
                o[nt][2*rr]   *= alpha;
                o[nt][2*rr+1] *= alpha;
            }
        }

        __syncthreads();   // all warps done reading KP as K
        // Write P (raw fp32 bits; mma truncates) into KP rows wq..wq+15
        #pragma unroll
        for (int nt = 0; nt < 8; nt++) {
            int base = (wq + g)*68 + nt*8 + 2*t;
            uint2 p0; p0.x = __float_as_uint(s[nt][0]); p0.y = __float_as_uint(s[nt][1]);
            uint2 p1; p1.x = __float_as_uint(s[nt][2]); p1.y = __float_as_uint(s[nt][3]);
            *(uint2*)&KP[base]        = p0;
            *(uint2*)&KP[base + 8*68] = p1;
        }
        __syncwarp();      // P rows are warp-private: warp-local ordering suffices

        // O += P V   (V stride 72: conflict-free B-frag loads)
        #pragma unroll
        for (int ks = 0; ks < 8; ks++) {
            unsigned pa[4];
            int base = (wq + g)*68 + ks*8 + t;
            pa[0] = KP[base];
            pa[1] = KP[base + 8*68];
            pa[2] = KP[base + 4];
            pa[3] = KP[base + 8*68 + 4];
            #pragma unroll
            for (int nt = 0; nt < 8; nt++) {
                unsigned bf[2];
                bf[0] = Vs[(ks*8 + t)*VST + nt*8 + g];
                bf[1] = Vs[(ks*8 + t + 4)*VST + nt*8 + g];
                mma8(o[nt], pa, bf, o[nt]);
            }
        }
    }

    // Epilogue
    float inv0 = 1.f / li[0], inv1 = 1.f / li[1];
    float* dst0 = g_attn + ((size_t)(b*S_ + q0 + wq + g))*DM_ + h*HD_;
    float* dst1 = dst0 + (size_t)8*DM_;
    #pragma unroll
    for (int nt = 0; nt < 8; nt++) {
        int c = nt*8 + 2*t;
        *(float2*)&dst0[c] = make_float2(o[nt][0]*inv0, o[nt][1]*inv0);
        *(float2*)&dst1[c] = make_float2(o[nt][2]*inv1, o[nt][3]*inv1);
    }
}

// ---------------------------------------------------------------------------
// LayerNorm: unbiased std (ddof=1), denominator (std + eps). One block per row.
// ---------------------------------------------------------------------------
__global__ __launch_bounds__(256)
void layernorm(const float* __restrict__ gamma, const float* __restrict__ beta,
               float* __restrict__ out)
{
    __shared__ float red[2][8];
    const int row = blockIdx.x;
    const int tid = threadIdx.x;
    const float* xr = g_x + (size_t)row * DM_;
    const int c = tid * 4;

    float4 xv = *(const float4*)(xr + c);
    float sum = xv.x + xv.y + xv.z + xv.w;
    float sq  = xv.x*xv.x + xv.y*xv.y + xv.z*xv.z + xv.w*xv.w;

    #pragma unroll
    for (int off = 16; off > 0; off >>= 1) {
        sum += __shfl_xor_sync(0xffffffffu, sum, off);
        sq  += __shfl_xor_sync(0xffffffffu, sq,  off);
    }
    const int w = tid >> 5, lane = tid & 31;
    if (lane == 0) { red[0][w] = sum; red[1][w] = sq; }
    __syncthreads();
    if (tid == 0) {
        float s = 0.f, q = 0.f;
        #pragma unroll
        for (int i = 0; i < 8; i++) { s += red[0][i]; q += red[1][i]; }
        red[0][0] = s; red[1][0] = q;
    }
    __syncthreads();
    sum = red[0][0]; sq = red[1][0];

    float mean = sum / (float)DM_;
    float var  = (sq - (float)DM_ * mean * mean) / (float)(DM_ - 1);
    var = fmaxf(var, 0.f);
    float inv = 1.f / (sqrtf(var) + 1e-6f);

    float4 g4 = *(const float4*)(gamma + c);
    float4 b4 = *(const float4*)(beta + c);
    float4 ov;
    ov.x = g4.x * (xv.x - mean) * inv + b4.x;
    ov.y = g4.y * (xv.y - mean) * inv + b4.y;
    ov.z = g4.z * (xv.z - mean) * inv + b4.z;
    ov.w = g4.w * (xv.w - mean) * inv + b4.w;
    *(float4*)(out + (size_t)row * DM_ + c) = ov;
}

// ---------------------------------------------------------------------------
extern "C" void kernel_launch(void* const* d_in, const int* in_sizes, int n_in,
                              void* d_out, int out_size)
{
    (void)in_sizes; (void)n_in; (void)out_size;
    const float* query = (const float*)d_in[0];
    const float* key_  = (const float*)d_in[1];
    const float* value = (const float*)d_in[2];
    const int*   mask  = (const int*)  d_in[3];
    const float* Wq = (const float*)d_in[4];
    const float* bq = (const float*)d_in[5];
    const float* Wk = (const float*)d_in[6];
    const float* bk = (const float*)d_in[7];
    const float* Wv = (const float*)d_in[8];
    const float* bv = (const float*)d_in[9];
    const float* Wo = (const float*)d_in[10];
    const float* bo = (const float*)d_in[11];
    const float* gamma = (const float*)d_in[12];
    const float* beta  = (const float*)d_in[13];
    float* out = (float*)d_out;

    tgemm_qkv<<<dim3(DM_/128, MTOT/128, 3), 256>>>(query, key_, value,
                                                   Wq, bq, Wk, bk, Wv, bv);

    flash_tc<<<dim3(S_/64, B_*H_), 128>>>(mask);

    tgemm_out<<<dim3(DM_/128, MTOT/128), 256>>>(Wo, bo, query);

    layernorm<<<MTOT, 256>>>(gamma, beta, out);
}

// round 12
// speedup vs baseline: 1.1128x; 1.0083x over previous
#include <cuda_runtime.h>
#include <math.h>

#define B_   2
#define S_   2048
#define DM_  1024
#define H_   16
#define HD_  64
#define MTOT (B_*S_)

// Scratch (alloc-free rule: __device__ globals)
__device__ float g_Q[MTOT*DM_];
__device__ float g_K[MTOT*DM_];
__device__ float g_V[MTOT*DM_];
__device__ float g_attn[MTOT*DM_];
__device__ float g_x[MTOT*DM_];

__device__ __forceinline__ unsigned f2tf(float f) {
    unsigned u; asm("cvt.rna.tf32.f32 %0, %1;" : "=r"(u) : "f"(f)); return u;
}

__device__ __forceinline__ void mma8(float* d, const unsigned* a, const unsigned* b, const float* c) {
    asm volatile("mma.sync.aligned.m16n8k8.row.col.f32.tf32.tf32.f32 "
        "{%0,%1,%2,%3}, {%4,%5,%6,%7}, {%8,%9}, {%10,%11,%12,%13};"
        : "=f"(d[0]), "=f"(d[1]), "=f"(d[2]), "=f"(d[3])
        : "r"(a[0]), "r"(a[1]), "r"(a[2]), "r"(a[3]),
          "r"(b[0]), "r"(b[1]),
          "f"(c[0]), "f"(c[1]), "f"(c[2]), "f"(c[3]));
}

// ---------------------------------------------------------------------------
// tf32 tensor-core GEMM (NT) — exact R2 structure (measured ~274us aggregate).
// One kernel launch per projection: W stays fully L2-resident per launch.
// C[m][n] = sum_k A[m][k]*W[n][k] + bias[n] (+res). 128x128 tile, BK=32,
// 256 threads (8 warps 2x4), warp tile 64x32, static smem stride 36.
// ---------------------------------------------------------------------------
template<bool ADD_RES>
__global__ __launch_bounds__(256)
void tgemm(const float* __restrict__ A, const float* __restrict__ W,
           const float* __restrict__ bias, const float* __restrict__ res, int which)
{
    __shared__ unsigned As[128*36];
    __shared__ unsigned Bs[128*36];

    const float* Abase = (A == nullptr) ? (const float*)g_attn : A;
    float* C = ADD_RES ? g_x : (which == 0 ? g_Q : (which == 1 ? g_K : g_V));

    const int tid = threadIdx.x;
    const int warp = tid >> 5, lane = tid & 31;
    const int g = lane >> 2, t = lane & 3;
    const int wm = warp >> 2, wn = warp & 3;       // 2 x 4 warp grid
    const int m0 = blockIdx.y * 128, n0 = blockIdx.x * 128;

    float acc[4][4][4];
    #pragma unroll
    for (int mt = 0; mt < 4; mt++)
        #pragma unroll
        for (int nt = 0; nt < 4; nt++)
            #pragma unroll
            for (int i = 0; i < 4; i++) acc[mt][nt][i] = 0.f;

    for (int k0 = 0; k0 < DM_; k0 += 32) {
        __syncthreads();
        #pragma unroll
        for (int i = 0; i < 4; i++) {
            int idx = tid + i*256;
            int r = idx >> 3, c = (idx & 7) << 2;
            float4 a4 = *(const float4*)(Abase + (size_t)(m0 + r)*DM_ + k0 + c);
            float4 w4 = *(const float4*)(W     + (size_t)(n0 + r)*DM_ + k0 + c);
            uint4 at; at.x = f2tf(a4.x); at.y = f2tf(a4.y); at.z = f2tf(a4.z); at.w = f2tf(a4.w);
            uint4 wt; wt.x = f2tf(w4.x); wt.y = f2tf(w4.y); wt.z = f2tf(w4.z); wt.w = f2tf(w4.w);
            *(uint4*)&As[r*36 + c] = at;
            *(uint4*)&Bs[r*36 + c] = wt;
        }
        __syncthreads();

        #pragma unroll
        for (int ks = 0; ks < 4; ks++) {
            unsigned af[4][4], bf[4][2];
            #pragma unroll
            for (int mt = 0; mt < 4; mt++) {
                int base = (wm*64 + mt*16 + g)*36 + ks*8 + t;
                af[mt][0] = As[base];
                af[mt][1] = As[base + 8*36];
                af[mt][2] = As[base + 4];
                af[mt][3] = As[base + 8*36 + 4];
            }
            #pragma unroll
            for (int nt = 0; nt < 4; nt++) {
                int base = (wn*32 + nt*8 + g)*36 + ks*8 + t;
                bf[nt][0] = Bs[base];
                bf[nt][1] = Bs[base + 4];
            }
            #pragma unroll
            for (int mt = 0; mt < 4; mt++)
                #pragma unroll
                for (int nt = 0; nt < 4; nt++)
                    mma8(acc[mt][nt], af[mt], bf[nt], acc[mt][nt]);
        }
    }

    #pragma unroll
    for (int mt = 0; mt < 4; mt++) {
        int row = m0 + wm*64 + mt*16 + g;
        #pragma unroll
        for (int nt = 0; nt < 4; nt++) {
            int col = n0 + wn*32 + nt*8 + 2*t;
            float2 bv = *(const float2*)&bias[col];
            float v0 = acc[mt][nt][0] + bv.x, v1 = acc[mt][nt][1] + bv.y;
            float v2 = acc[mt][nt][2] + bv.x, v3 = acc[mt][nt][3] + bv.y;
            if (ADD_RES) {
                float2 r0 = *(const float2*)&res[(size_t)row*DM_ + col];
                float2 r1 = *(const float2*)&res[(size_t)(row+8)*DM_ + col];
                v0 += r0.x; v1 += r0.y; v2 += r1.x; v3 += r1.y;
            }
            *(float2*)&C[(size_t)row*DM_ + col]     = make_float2(v0, v1);
            *(float2*)&C[(size_t)(row+8)*DM_ + col] = make_float2(v2, v3);
        }
    }
}

// ---------------------------------------------------------------------------
// Flash attention with tf32 mma.sync — R11 body (measured ~370us):
//  V smem stride 72 (conflict-free PV B-frags), warp-private P (syncwarp).
// Block = 128 threads (4 warps), 64 query rows. smem ~35.8 KB static.
// ---------------------------------------------------------------------------
#define VST 72

__global__ __launch_bounds__(128)
void flash_tc(const int* __restrict__ mask)
{
    __shared__ unsigned KP[64*68];
    __shared__ unsigned Vs[64*VST];

    const int tid = threadIdx.x;
    const int warp = tid >> 5, lane = tid & 31;
    const int g = lane >> 2, t = lane & 3;
    const int q0 = blockIdx.x * 64;
    const int bh = blockIdx.y, b = bh >> 4, h = bh & 15;
    const int wq = warp * 16;
    const float scale = 0.125f;

    // Load Q tile into KP, extract fragments, then KP is free for K.
    {
        const float* src = g_Q + ((size_t)(b*S_ + q0))*DM_ + h*HD_;
        #pragma unroll
        for (int i = 0; i < 8; i++) {
            int idx = tid + i*128;
            int r = idx >> 4, c = (idx & 15) << 2;
            float4 v = *(const float4*)(src + (size_t)r*DM_ + c);
            uint4 u; u.x = f2tf(v.x*scale); u.y = f2tf(v.y*scale);
                     u.z = f2tf(v.z*scale); u.w = f2tf(v.w*scale);
            *(uint4*)&KP[r*68 + c] = u;
        }
    }
    __syncthreads();

    unsigned qf[8][4];
    #pragma unroll
    for (int ks = 0; ks < 8; ks++) {
        int base = (wq + g)*68 + ks*8 + t;
        qf[ks][0] = KP[base];
        qf[ks][1] = KP[base + 8*68];
        qf[ks][2] = KP[base + 4];
        qf[ks][3] = KP[base + 8*68 + 4];
    }

    float o[8][4];
    #pragma unroll
    for (int nt = 0; nt < 8; nt++)
        #pragma unroll
        for (int i = 0; i < 4; i++) o[nt][i] = 0.f;
    float mi[2] = {-1e30f, -1e30f}, li[2] = {0.f, 0.f};

    const int* mrow0 = mask + ((size_t)b*S_ + q0 + wq + g)*S_;
    const int* mrow1 = mrow0 + 8*S_;

    for (int k0 = 0; k0 < S_; k0 += 64) {
        __syncthreads();   // previous tile's PV done reading KP(P rows)/Vs
        {
            const float* ksrc = g_K + ((size_t)(b*S_ + k0))*DM_ + h*HD_;
            const float* vsrc = g_V + ((size_t)(b*S_ + k0))*DM_ + h*HD_;
            #pragma unroll
            for (int i = 0; i < 8; i++) {
                int idx = tid + i*128;
                int r = idx >> 4, c = (idx & 15) << 2;
                float4 kv = *(const float4*)(ksrc + (size_t)r*DM_ + c);
                float4 vv = *(const float4*)(vsrc + (size_t)r*DM_ + c);
                uint4 ku; ku.x = f2tf(kv.x); ku.y = f2tf(kv.y); ku.z = f2tf(kv.z); ku.w = f2tf(kv.w);
                uint4 vu; vu.x = f2tf(vv.x); vu.y = f2tf(vv.y); vu.z = f2tf(vv.z); vu.w = f2tf(vv.w);
                *(uint4*)&KP[r*68 + c]  = ku;
                *(uint4*)&Vs[r*VST + c] = vu;
            }
        }
        __syncthreads();

        // S = Q K^T
        float s[8][4];
        #pragma unroll
        for (int nt = 0; nt < 8; nt++)
            #pragma unroll
            for (int i = 0; i < 4; i++) s[nt][i] = 0.f;

        #pragma unroll
        for (int ks = 0; ks < 8; ks++) {
            #pragma unroll
            for (int nt = 0; nt < 8; nt++) {
                unsigned bf[2];
                int base = (nt*8 + g)*68 + ks*8 + t;
                bf[0] = KP[base];
                bf[1] = KP[base + 4];
                mma8(s[nt], qf[ks], bf, s[nt]);
            }
        }

        // Mask
        #pragma unroll
        for (int nt = 0; nt < 8; nt++) {
            int c = k0 + nt*8 + 2*t;
            int2 m0v = *(const int2*)&mrow0[c];
            int2 m1v = *(const int2*)&mrow1[c];
            if (m0v.x == 0) s[nt][0] = -1e9f;
            if (m0v.y == 0) s[nt][1] = -1e9f;
            if (m1v.x == 0) s[nt][2] = -1e9f;
            if (m1v.y == 0) s[nt][3] = -1e9f;
        }

        // Online softmax; rr=0 -> frag slots 0,1 (row g); rr=1 -> 2,3 (row g+8)
        #pragma unroll
        for (int rr = 0; rr < 2; rr++) {
            float mx = -1e30f;
            #pragma unroll
            for (int nt = 0; nt < 8; nt++)
                mx = fmaxf(mx, fmaxf(s[nt][2*rr], s[nt][2*rr+1]));
            mx = fmaxf(mx, __shfl_xor_sync(0xffffffffu, mx, 1));
            mx = fmaxf(mx, __shfl_xor_sync(0xffffffffu, mx, 2));
            float mnew = fmaxf(mi[rr], mx);
            float alpha = __expf(mi[rr] - mnew);
            float sum = 0.f;
            #pragma unroll
            for (int nt = 0; nt < 8; nt++) {
                s[nt][2*rr]   = __expf(s[nt][2*rr]   - mnew);
                s[nt][2*rr+1] = __expf(s[nt][2*rr+1] - mnew);
                sum += s[nt][2*rr] + s[nt][2*rr+1];
            }
            sum += __shfl_xor_sync(0xffffffffu, sum, 1);
            sum += __shfl_xor_sync(0xffffffffu, sum, 2);
            li[rr] = li[rr]*alpha + sum;
            mi[rr] = mnew;
            #pragma unroll
            for (int nt = 0; nt < 8; nt++) {
                o[nt][2*rr]   *= alpha;
                o[nt][2*rr+1] *= alpha;
            }
        }

        __syncthreads();   // all warps done reading KP as K
        // Write P (raw fp32 bits; mma truncates) into KP rows wq..wq+15
        #pragma unroll
        for (int nt = 0; nt < 8; nt++) {
            int base = (wq + g)*68 + nt*8 + 2*t;
            uint2 p0; p0.x = __float_as_uint(s[nt][0]); p0.y = __float_as_uint(s[nt][1]);
            uint2 p1; p1.x = __float_as_uint(s[nt][2]); p1.y = __float_as_uint(s[nt][3]);
            *(uint2*)&KP[base]        = p0;
            *(uint2*)&KP[base + 8*68] = p1;
        }
        __syncwarp();      // P rows are warp-private: warp-local ordering suffices

        // O += P V   (V stride 72: conflict-free B-frag loads)
        #pragma unroll
        for (int ks = 0; ks < 8; ks++) {
            unsigned pa[4];
            int base = (wq + g)*68 + ks*8 + t;
            pa[0] = KP[base];
            pa[1] = KP[base + 8*68];
            pa[2] = KP[base + 4];
            pa[3] = KP[base + 8*68 + 4];
            #pragma unroll
            for (int nt = 0; nt < 8; nt++) {
                unsigned bf[2];
                bf[0] = Vs[(ks*8 + t)*VST + nt*8 + g];
                bf[1] = Vs[(ks*8 + t + 4)*VST + nt*8 + g];
                mma8(o[nt], pa, bf, o[nt]);
            }
        }
    }

    // Epilogue
    float inv0 = 1.f / li[0], inv1 = 1.f / li[1];
    float* dst0 = g_attn + ((size_t)(b*S_ + q0 + wq + g))*DM_ + h*HD_;
    float* dst1 = dst0 + (size_t)8*DM_;
    #pragma unroll
    for (int nt = 0; nt < 8; nt++) {
        int c = nt*8 + 2*t;
        *(float2*)&dst0[c] = make_float2(o[nt][0]*inv0, o[nt][1]*inv0);
        *(float2*)&dst1[c] = make_float2(o[nt][2]*inv1, o[nt][3]*inv1);
    }
}

// ---------------------------------------------------------------------------
// LayerNorm: unbiased std (ddof=1), denominator (std + eps). One block per row.
// ---------------------------------------------------------------------------
__global__ __launch_bounds__(256)
void layernorm(const float* __restrict__ gamma, const float* __restrict__ beta,
               float* __restrict__ out)
{
    __shared__ float red[2][8];
    const int row = blockIdx.x;
    const int tid = threadIdx.x;
    const float* xr = g_x + (size_t)row * DM_;
    const int c = tid * 4;

    float4 xv = *(const float4*)(xr + c);
    float sum = xv.x + xv.y + xv.z + xv.w;
    float sq  = xv.x*xv.x + xv.y*xv.y + xv.z*xv.z + xv.w*xv.w;

    #pragma unroll
    for (int off = 16; off > 0; off >>= 1) {
        sum += __shfl_xor_sync(0xffffffffu, sum, off);
        sq  += __shfl_xor_sync(0xffffffffu, sq,  off);
    }
    const int w = tid >> 5, lane = tid & 31;
    if (lane == 0) { red[0][w] = sum; red[1][w] = sq; }
    __syncthreads();
    if (tid == 0) {
        float s = 0.f, q = 0.f;
        #pragma unroll
        for (int i = 0; i < 8; i++) { s += red[0][i]; q += red[1][i]; }
        red[0][0] = s; red[1][0] = q;
    }
    __syncthreads();
    sum = red[0][0]; sq = red[1][0];

    float mean = sum / (float)DM_;
    float var  = (sq - (float)DM_ * mean * mean) / (float)(DM_ - 1);
    var = fmaxf(var, 0.f);
    float inv = 1.f / (sqrtf(var) + 1e-6f);

    float4 g4 = *(const float4*)(gamma + c);
    float4 b4 = *(const float4*)(beta + c);
    float4 ov;
    ov.x = g4.x * (xv.x - mean) * inv + b4.x;
    ov.y = g4.y * (xv.y - mean) * inv + b4.y;
    ov.z = g4.z * (xv.z - mean) * inv + b4.z;
    ov.w = g4.w * (xv.w - mean) * inv + b4.w;
    *(float4*)(out + (size_t)row * DM_ + c) = ov;
}

// ---------------------------------------------------------------------------
extern "C" void kernel_launch(void* const* d_in, const int* in_sizes, int n_in,
                              void* d_out, int out_size)
{
    (void)in_sizes; (void)n_in; (void)out_size;
    const float* query = (const float*)d_in[0];
    const float* key_  = (const float*)d_in[1];
    const float* value = (const float*)d_in[2];
    const int*   mask  = (const int*)  d_in[3];
    const float* Wq = (const float*)d_in[4];
    const float* bq = (const float*)d_in[5];
    const float* Wk = (const float*)d_in[6];
    const float* bk = (const float*)d_in[7];
    const float* Wv = (const float*)d_in[8];
    const float* bv = (const float*)d_in[9];
    const float* Wo = (const float*)d_in[10];
    const float* bo = (const float*)d_in[11];
    const float* gamma = (const float*)d_in[12];
    const float* beta  = (const float*)d_in[13];
    float* out = (float*)d_out;

    dim3 gg(DM_/128, MTOT/128);   // (8, 32)
    tgemm<false><<<gg, 256>>>(query, Wq, bq, nullptr, 0);
    tgemm<false><<<gg, 256>>>(key_,  Wk, bk, nullptr, 1);
    tgemm<false><<<gg, 256>>>(value, Wv, bv, nullptr, 2);

    flash_tc<<<dim3(S_/64, B_*H_), 128>>>(mask);

    tgemm<true><<<gg, 256>>>(nullptr, Wo, bo, query, 3);

    layernorm<<<MTOT, 256>>>(gamma, beta, out);
}

// round 13
// speedup vs baseline: 1.3121x; 1.1791x over previous
#include <cuda_runtime.h>
#include <math.h>

#define B_   2
#define S_   2048
#define DM_  1024
#define H_   16
#define HD_  64
#define MTOT (B_*S_)

// Scratch (alloc-free rule: __device__ globals)
__device__ float g_Q[MTOT*DM_];
__device__ float g_K[MTOT*DM_];
__device__ float g_V[MTOT*DM_];
__device__ float g_attn[MTOT*DM_];
__device__ float g_x[MTOT*DM_];

__device__ __forceinline__ unsigned f2tf(float f) {
    unsigned u; asm("cvt.rna.tf32.f32 %0, %1;" : "=r"(u) : "f"(f)); return u;
}

__device__ __forceinline__ void mma8(float* d, const unsigned* a, const unsigned* b, const float* c) {
    asm volatile("mma.sync.aligned.m16n8k8.row.col.f32.tf32.tf32.f32 "
        "{%0,%1,%2,%3}, {%4,%5,%6,%7}, {%8,%9}, {%10,%11,%12,%13};"
        : "=f"(d[0]), "=f"(d[1]), "=f"(d[2]), "=f"(d[3])
        : "r"(a[0]), "r"(a[1]), "r"(a[2]), "r"(a[3]),
          "r"(b[0]), "r"(b[1]),
          "f"(c[0]), "f"(c[1]), "f"(c[2]), "f"(c[3]));
}

// ---------------------------------------------------------------------------
// tf32 tensor-core GEMM (NT) — R2 structure, separate launches (measured ~263us).
// C[m][n] = sum_k A[m][k]*W[n][k] + bias[n] (+res). 128x128 tile, BK=32,
// 256 threads (8 warps 2x4), warp tile 64x32, static smem stride 36.
// ---------------------------------------------------------------------------
template<bool ADD_RES>
__global__ __launch_bounds__(256)
void tgemm(const float* __restrict__ A, const float* __restrict__ W,
           const float* __restrict__ bias, const float* __restrict__ res, int which)
{
    __shared__ unsigned As[128*36];
    __shared__ unsigned Bs[128*36];

    const float* Abase = (A == nullptr) ? (const float*)g_attn : A;
    float* C = ADD_RES ? g_x : (which == 0 ? g_Q : (which == 1 ? g_K : g_V));

    const int tid = threadIdx.x;
    const int warp = tid >> 5, lane = tid & 31;
    const int g = lane >> 2, t = lane & 3;
    const int wm = warp >> 2, wn = warp & 3;       // 2 x 4 warp grid
    const int m0 = blockIdx.y * 128, n0 = blockIdx.x * 128;

    float acc[4][4][4];
    #pragma unroll
    for (int mt = 0; mt < 4; mt++)
        #pragma unroll
        for (int nt = 0; nt < 4; nt++)
            #pragma unroll
            for (int i = 0; i < 4; i++) acc[mt][nt][i] = 0.f;

    for (int k0 = 0; k0 < DM_; k0 += 32) {
        __syncthreads();
        #pragma unroll
        for (int i = 0; i < 4; i++) {
            int idx = tid + i*256;
            int r = idx >> 3, c = (idx & 7) << 2;
            float4 a4 = *(const float4*)(Abase + (size_t)(m0 + r)*DM_ + k0 + c);
            float4 w4 = *(const float4*)(W     + (size_t)(n0 + r)*DM_ + k0 + c);
            uint4 at; at.x = f2tf(a4.x); at.y = f2tf(a4.y); at.z = f2tf(a4.z); at.w = f2tf(a4.w);
            uint4 wt; wt.x = f2tf(w4.x); wt.y = f2tf(w4.y); wt.z = f2tf(w4.z); wt.w = f2tf(w4.w);
            *(uint4*)&As[r*36 + c] = at;
            *(uint4*)&Bs[r*36 + c] = wt;
        }
        __syncthreads();

        #pragma unroll
        for (int ks = 0; ks < 4; ks++) {
            unsigned af[4][4], bf[4][2];
            #pragma unroll
            for (int mt = 0; mt < 4; mt++) {
                int base = (wm*64 + mt*16 + g)*36 + ks*8 + t;
                af[mt][0] = As[base];
                af[mt][1] = As[base + 8*36];
                af[mt][2] = As[base + 4];
                af[mt][3] = As[base + 8*36 + 4];
            }
            #pragma unroll
            for (int nt = 0; nt < 4; nt++) {
                int base = (wn*32 + nt*8 + g)*36 + ks*8 + t;
                bf[nt][0] = Bs[base];
                bf[nt][1] = Bs[base + 4];
            }
            #pragma unroll
            for (int mt = 0; mt < 4; mt++)
                #pragma unroll
                for (int nt = 0; nt < 4; nt++)
                    mma8(acc[mt][nt], af[mt], bf[nt], acc[mt][nt]);
        }
    }

    #pragma unroll
    for (int mt = 0; mt < 4; mt++) {
        int row = m0 + wm*64 + mt*16 + g;
        #pragma unroll
        for (int nt = 0; nt < 4; nt++) {
            int col = n0 + wn*32 + nt*8 + 2*t;
            float2 bv = *(const float2*)&bias[col];
            float v0 = acc[mt][nt][0] + bv.x, v1 = acc[mt][nt][1] + bv.y;
            float v2 = acc[mt][nt][2] + bv.x, v3 = acc[mt][nt][3] + bv.y;
            if (ADD_RES) {
                float2 r0 = *(const float2*)&res[(size_t)row*DM_ + col];
                float2 r1 = *(const float2*)&res[(size_t)(row+8)*DM_ + col];
                v0 += r0.x; v1 += r0.y; v2 += r1.x; v3 += r1.y;
            }
            *(float2*)&C[(size_t)row*DM_ + col]     = make_float2(v0, v1);
            *(float2*)&C[(size_t)(row+8)*DM_ + col] = make_float2(v2, v3);
        }
    }
}

// ---------------------------------------------------------------------------
// Flash attention with tf32 mma.sync — EXACT R2 body (80 regs, 410us) with
// ONE change: Vs stride 72 (=8 mod 32) so PV B-frag bank = 8t+8nt+g, a
// bijection over lanes -> conflict-free (stride 68 was 2-way conflicted).
// Both __syncthreads and f2tf P-writes retained (register-pressure control).
// Block = 128 threads (4 warps), 64 query rows. smem ~35.8 KB static.
// ---------------------------------------------------------------------------
#define VST 72

__global__ __launch_bounds__(128)
void flash_tc(const int* __restrict__ mask)
{
    __shared__ unsigned KP[64*68];
    __shared__ unsigned Vs[64*VST];

    const int tid = threadIdx.x;
    const int warp = tid >> 5, lane = tid & 31;
    const int g = lane >> 2, t = lane & 3;
    const int q0 = blockIdx.x * 64;
    const int bh = blockIdx.y, b = bh >> 4, h = bh & 15;
    const int wq = warp * 16;
    const float scale = 0.125f;

    // Load Q tile into KP, extract fragments, then KP is free for K.
    {
        const float* src = g_Q + ((size_t)(b*S_ + q0))*DM_ + h*HD_;
        #pragma unroll
        for (int i = 0; i < 8; i++) {
            int idx = tid + i*128;
            int r = idx >> 4, c = (idx & 15) << 2;
            float4 v = *(const float4*)(src + (size_t)r*DM_ + c);
            uint4 u; u.x = f2tf(v.x*scale); u.y = f2tf(v.y*scale);
                     u.z = f2tf(v.z*scale); u.w = f2tf(v.w*scale);
            *(uint4*)&KP[r*68 + c] = u;
        }
    }
    __syncthreads();

    unsigned qf[8][4];
    #pragma unroll
    for (int ks = 0; ks < 8; ks++) {
        int base = (wq + g)*68 + ks*8 + t;
        qf[ks][0] = KP[base];
        qf[ks][1] = KP[base + 8*68];
        qf[ks][2] = KP[base + 4];
        qf[ks][3] = KP[base + 8*68 + 4];
    }

    float o[8][4];
    #pragma unroll
    for (int nt = 0; nt < 8; nt++)
        #pragma unroll
        for (int i = 0; i < 4; i++) o[nt][i] = 0.f;
    float mi[2] = {-1e30f, -1e30f}, li[2] = {0.f, 0.f};

    const int* mrow0 = mask + ((size_t)b*S_ + q0 + wq + g)*S_;
    const int* mrow1 = mrow0 + 8*S_;

    for (int k0 = 0; k0 < S_; k0 += 64) {
        __syncthreads();  // previous iteration done reading KP/Vs
        {
            const float* ksrc = g_K + ((size_t)(b*S_ + k0))*DM_ + h*HD_;
            const float* vsrc = g_V + ((size_t)(b*S_ + k0))*DM_ + h*HD_;
            #pragma unroll
            for (int i = 0; i < 8; i++) {
                int idx = tid + i*128;
                int r = idx >> 4, c = (idx & 15) << 2;
                float4 kv = *(const float4*)(ksrc + (size_t)r*DM_ + c);
                float4 vv = *(const float4*)(vsrc + (size_t)r*DM_ + c);
                uint4 ku; ku.x = f2tf(kv.x); ku.y = f2tf(kv.y); ku.z = f2tf(kv.z); ku.w = f2tf(kv.w);
                uint4 vu; vu.x = f2tf(vv.x); vu.y = f2tf(vv.y); vu.z = f2tf(vv.z); vu.w = f2tf(vv.w);
                *(uint4*)&KP[r*68 + c]  = ku;
                *(uint4*)&Vs[r*VST + c] = vu;
            }
        }
        __syncthreads();

        // S = Q K^T
        float s[8][4];
        #pragma unroll
        for (int nt = 0; nt < 8; nt++)
            #pragma unroll
            for (int i = 0; i < 4; i++) s[nt][i] = 0.f;

        #pragma unroll
        for (int ks = 0; ks < 8; ks++) {
            #pragma unroll
            for (int nt = 0; nt < 8; nt++) {
                unsigned bf[2];
                int base = (nt*8 + g)*68 + ks*8 + t;
                bf[0] = KP[base];
                bf[1] = KP[base + 4];
                mma8(s[nt], qf[ks], bf, s[nt]);
            }
        }

        // Mask
        #pragma unroll
        for (int nt = 0; nt < 8; nt++) {
            int c = k0 + nt*8 + 2*t;
            int2 m0v = *(const int2*)&mrow0[c];
            int2 m1v = *(const int2*)&mrow1[c];
            if (m0v.x == 0) s[nt][0] = -1e9f;
            if (m0v.y == 0) s[nt][1] = -1e9f;
            if (m1v.x == 0) s[nt][2] = -1e9f;
            if (m1v.y == 0) s[nt][3] = -1e9f;
        }

        // Online softmax; rr=0 -> frag slots 0,1 (row g); rr=1 -> 2,3 (row g+8)
        #pragma unroll
        for (int rr = 0; rr < 2; rr++) {
            float mx = -1e30f;
            #pragma unroll
            for (int nt = 0; nt < 8; nt++)
                mx = fmaxf(mx, fmaxf(s[nt][2*rr], s[nt][2*rr+1]));
            mx = fmaxf(mx, __shfl_xor_sync(0xffffffffu, mx, 1));
            mx = fmaxf(mx, __shfl_xor_sync(0xffffffffu, mx, 2));
            float mnew = fmaxf(mi[rr], mx);
            float alpha = __expf(mi[rr] - mnew);
            float sum = 0.f;
            #pragma unroll
            for (int nt = 0; nt < 8; nt++) {
                s[nt][2*rr]   = __expf(s[nt][2*rr]   - mnew);
                s[nt][2*rr+1] = __expf(s[nt][2*rr+1] - mnew);
                sum += s[nt][2*rr] + s[nt][2*rr+1];
            }
            sum += __shfl_xor_sync(0xffffffffu, sum, 1);
            sum += __shfl_xor_sync(0xffffffffu, sum, 2);
            li[rr] = li[rr]*alpha + sum;
            mi[rr] = mnew;
            #pragma unroll
            for (int nt = 0; nt < 8; nt++) {
                o[nt][2*rr]   *= alpha;
                o[nt][2*rr+1] *= alpha;
            }
        }

        __syncthreads();   // all warps done reading KP as K
        // Write P (tf32) into KP: P[q][key], stride 68
        #pragma unroll
        for (int nt = 0; nt < 8; nt++) {
            int base = (wq + g)*68 + nt*8 + 2*t;
            uint2 p0; p0.x = f2tf(s[nt][0]); p0.y = f2tf(s[nt][1]);
            uint2 p1; p1.x = f2tf(s[nt][2]); p1.y = f2tf(s[nt][3]);
            *(uint2*)&KP[base]        = p0;
            *(uint2*)&KP[base + 8*68] = p1;
        }
        __syncthreads();

        // O += P V   (V stride 72: conflict-free B-frag loads)
        #pragma unroll
        for (int ks = 0; ks < 8; ks++) {
            unsigned pa[4];
            int base = (wq + g)*68 + ks*8 + t;
            pa[0] = KP[base];
            pa[1] = KP[base + 8*68];
            pa[2] = KP[base + 4];
            pa[3] = KP[base + 8*68 + 4];
            #pragma unroll
            for (int nt = 0; nt < 8; nt++) {
                unsigned bf[2];
                bf[0] = Vs[(ks*8 + t)*VST + nt*8 + g];
                bf[1] = Vs[(ks*8 + t + 4)*VST + nt*8 + g];
                mma8(o[nt], pa, bf, o[nt]);
            }
        }
    }

    // Epilogue
    float inv0 = 1.f / li[0], inv1 = 1.f / li[1];
    float* dst0 = g_attn + ((size_t)(b*S_ + q0 + wq + g))*DM_ + h*HD_;
    float* dst1 = dst0 + (size_t)8*DM_;
    #pragma unroll
    for (int nt = 0; nt < 8; nt++) {
        int c = nt*8 + 2*t;
        *(float2*)&dst0[c] = make_float2(o[nt][0]*inv0, o[nt][1]*inv0);
        *(float2*)&dst1[c] = make_float2(o[nt][2]*inv1, o[nt][3]*inv1);
    }
}

// ---------------------------------------------------------------------------
// LayerNorm: unbiased std (ddof=1), denominator (std + eps). One block per row.
// ---------------------------------------------------------------------------
__global__ __launch_bounds__(256)
void layernorm(const float* __restrict__ gamma, const float* __restrict__ beta,
               float* __restrict__ out)
{
    __shared__ float red[2][8];
    const int row = blockIdx.x;
    const int tid = threadIdx.x;
    const float* xr = g_x + (size_t)row * DM_;
    const int c = tid * 4;

    float4 xv = *(const float4*)(xr + c);
    float sum = xv.x + xv.y + xv.z + xv.w;
    float sq  = xv.x*xv.x + xv.y*xv.y + xv.z*xv.z + xv.w*xv.w;

    #pragma unroll
    for (int off = 16; off > 0; off >>= 1) {
        sum += __shfl_xor_sync(0xffffffffu, sum, off);
        sq  += __shfl_xor_sync(0xffffffffu, sq,  off);
    }
    const int w = tid >> 5, lane = tid & 31;
    if (lane == 0) { red[0][w] = sum; red[1][w] = sq; }
    __syncthreads();
    if (tid == 0) {
        float s = 0.f, q = 0.f;
        #pragma unroll
        for (int i = 0; i < 8; i++) { s += red[0][i]; q += red[1][i]; }
        red[0][0] = s; red[1][0] = q;
    }
    __syncthreads();
    sum = red[0][0]; sq = red[1][0];

    float mean = sum / (float)DM_;
    float var  = (sq - (float)DM_ * mean * mean) / (float)(DM_ - 1);
    var = fmaxf(var, 0.f);
    float inv = 1.f / (sqrtf(var) + 1e-6f);

    float4 g4 = *(const float4*)(gamma + c);
    float4 b4 = *(const float4*)(beta + c);
    float4 ov;
    ov.x = g4.x * (xv.x - mean) * inv + b4.x;
    ov.y = g4.y * (xv.y - mean) * inv + b4.y;
    ov.z = g4.z * (xv.z - mean) * inv + b4.z;
    ov.w = g4.w * (xv.w - mean) * inv + b4.w;
    *(float4*)(out + (size_t)row * DM_ + c) = ov;
}

// ---------------------------------------------------------------------------
extern "C" void kernel_launch(void* const* d_in, const int* in_sizes, int n_in,
                              void* d_out, int out_size)
{
    (void)in_sizes; (void)n_in; (void)out_size;
    const float* query = (const float*)d_in[0];
    const float* key_  = (const float*)d_in[1];
    const float* value = (const float*)d_in[2];
    const int*   mask  = (const int*)  d_in[3];
    const float* Wq = (const float*)d_in[4];
    const float* bq = (const float*)d_in[5];
    const float* Wk = (const float*)d_in[6];
    const float* bk = (const float*)d_in[7];
    const float* Wv = (const float*)d_in[8];
    const float* bv = (const float*)d_in[9];
    const float* Wo = (const float*)d_in[10];
    const float* bo = (const float*)d_in[11];
    const float* gamma = (const float*)d_in[12];
    const float* beta  = (const float*)d_in[13];
    float* out = (float*)d_out;

    dim3 gg(DM_/128, MTOT/128);   // (8, 32)
    tgemm<false><<<gg, 256>>>(query, Wq, bq, nullptr, 0);
    tgemm<false><<<gg, 256>>>(key_,  Wk, bk, nullptr, 1);
    tgemm<false><<<gg, 256>>>(value, Wv, bv, nullptr, 2);

    flash_tc<<<dim3(S_/64, B_*H_), 128>>>(mask);

    tgemm<true><<<gg, 256>>>(nullptr, Wo, bo, query, 3);

    layernorm<<<MTOT, 256>>>(gamma, beta, out);
}

// round 14
// speedup vs baseline: 1.5416x; 1.1749x over previous
#include <cuda_runtime.h>
#include <math.h>

#define B_   2
#define S_   2048
#define DM_  1024
#define H_   16
#define HD_  64
#define MTOT (B_*S_)

// Scratch (alloc-free rule: __device__ globals)
__device__ float g_Q[MTOT*DM_];
__device__ float g_K[MTOT*DM_];
__device__ float g_V[MTOT*DM_];
__device__ float g_attn[MTOT*DM_];
__device__ float g_x[MTOT*DM_];

__device__ __forceinline__ unsigned f2tf(float f) {
    unsigned u; asm("cvt.rna.tf32.f32 %0, %1;" : "=r"(u) : "f"(f)); return u;
}

// pack two fp32 -> bf16x2 (lo = first arg, hi = second arg)
__device__ __forceinline__ unsigned packbf(float lo, float hi) {
    unsigned r; asm("cvt.rn.bf16x2.f32 %0, %1, %2;" : "=r"(r) : "f"(hi), "f"(lo));
    return r;
}

__device__ __forceinline__ void mma8(float* d, const unsigned* a, const unsigned* b, const float* c) {
    asm volatile("mma.sync.aligned.m16n8k8.row.col.f32.tf32.tf32.f32 "
        "{%0,%1,%2,%3}, {%4,%5,%6,%7}, {%8,%9}, {%10,%11,%12,%13};"
        : "=f"(d[0]), "=f"(d[1]), "=f"(d[2]), "=f"(d[3])
        : "r"(a[0]), "r"(a[1]), "r"(a[2]), "r"(a[3]),
          "r"(b[0]), "r"(b[1]),
          "f"(c[0]), "f"(c[1]), "f"(c[2]), "f"(c[3]));
}

// bf16 m16n8k16 mma, fp32 accumulate (in-place)
__device__ __forceinline__ void mma16(float* d, const unsigned* a, unsigned b0, unsigned b1) {
    asm volatile("mma.sync.aligned.m16n8k16.row.col.f32.bf16.bf16.f32 "
        "{%0,%1,%2,%3}, {%4,%5,%6,%7}, {%8,%9}, {%0,%1,%2,%3};"
        : "+f"(d[0]), "+f"(d[1]), "+f"(d[2]), "+f"(d[3])
        : "r"(a[0]), "r"(a[1]), "r"(a[2]), "r"(a[3]),
          "r"(b0), "r"(b1));
}

#define LDSM4(r0,r1,r2,r3, addr) \
    asm volatile("ldmatrix.sync.aligned.m8n8.x4.shared.b16 {%0,%1,%2,%3}, [%4];" \
        : "=r"(r0), "=r"(r1), "=r"(r2), "=r"(r3) : "r"(addr))
#define LDSM4T(r0,r1,r2,r3, addr) \
    asm volatile("ldmatrix.sync.aligned.m8n8.x4.trans.shared.b16 {%0,%1,%2,%3}, [%4];" \
        : "=r"(r0), "=r"(r1), "=r"(r2), "=r"(r3) : "r"(addr))

// ---------------------------------------------------------------------------
// tf32 tensor-core GEMM (NT) — R13 body unchanged (measured ~263us aggregate).
// ---------------------------------------------------------------------------
template<bool ADD_RES>
__global__ __launch_bounds__(256)
void tgemm(const float* __restrict__ A, const float* __restrict__ W,
           const float* __restrict__ bias, const float* __restrict__ res, int which)
{
    __shared__ unsigned As[128*36];
    __shared__ unsigned Bs[128*36];

    const float* Abase = (A == nullptr) ? (const float*)g_attn : A;
    float* C = ADD_RES ? g_x : (which == 0 ? g_Q : (which == 1 ? g_K : g_V));

    const int tid = threadIdx.x;
    const int warp = tid >> 5, lane = tid & 31;
    const int g = lane >> 2, t = lane & 3;
    const int wm = warp >> 2, wn = warp & 3;
    const int m0 = blockIdx.y * 128, n0 = blockIdx.x * 128;

    float acc[4][4][4];
    #pragma unroll
    for (int mt = 0; mt < 4; mt++)
        #pragma unroll
        for (int nt = 0; nt < 4; nt++)
            #pragma unroll
            for (int i = 0; i < 4; i++) acc[mt][nt][i] = 0.f;

    for (int k0 = 0; k0 < DM_; k0 += 32) {
        __syncthreads();
        #pragma unroll
        for (int i = 0; i < 4; i++) {
            int idx = tid + i*256;
            int r = idx >> 3, c = (idx & 7) << 2;
            float4 a4 = *(const float4*)(Abase + (size_t)(m0 + r)*DM_ + k0 + c);
            float4 w4 = *(const float4*)(W     + (size_t)(n0 + r)*DM_ + k0 + c);
            uint4 at; at.x = f2tf(a4.x); at.y = f2tf(a4.y); at.z = f2tf(a4.z); at.w = f2tf(a4.w);
            uint4 wt; wt.x = f2tf(w4.x); wt.y = f2tf(w4.y); wt.z = f2tf(w4.z); wt.w = f2tf(w4.w);
            *(uint4*)&As[r*36 + c] = at;
            *(uint4*)&Bs[r*36 + c] = wt;
        }
        __syncthreads();

        #pragma unroll
        for (int ks = 0; ks < 4; ks++) {
            unsigned af[4][4], bf[4][2];
            #pragma unroll
            for (int mt = 0; mt < 4; mt++) {
                int base = (wm*64 + mt*16 + g)*36 + ks*8 + t;
                af[mt][0] = As[base];
                af[mt][1] = As[base + 8*36];
                af[mt][2] = As[base + 4];
                af[mt][3] = As[base + 8*36 + 4];
            }
            #pragma unroll
            for (int nt = 0; nt < 4; nt++) {
                int base = (wn*32 + nt*8 + g)*36 + ks*8 + t;
                bf[nt][0] = Bs[base];
                bf[nt][1] = Bs[base + 4];
            }
            #pragma unroll
            for (int mt = 0; mt < 4; mt++)
                #pragma unroll
                for (int nt = 0; nt < 4; nt++)
                    mma8(acc[mt][nt], af[mt], bf[nt], acc[mt][nt]);
        }
    }

    #pragma unroll
    for (int mt = 0; mt < 4; mt++) {
        int row = m0 + wm*64 + mt*16 + g;
        #pragma unroll
        for (int nt = 0; nt < 4; nt++) {
            int col = n0 + wn*32 + nt*8 + 2*t;
            float2 bv = *(const float2*)&bias[col];
            float v0 = acc[mt][nt][0] + bv.x, v1 = acc[mt][nt][1] + bv.y;
            float v2 = acc[mt][nt][2] + bv.x, v3 = acc[mt][nt][3] + bv.y;
            if (ADD_RES) {
                float2 r0 = *(const float2*)&res[(size_t)row*DM_ + col];
                float2 r1 = *(const float2*)&res[(size_t)(row+8)*DM_ + col];
                v0 += r0.x; v1 += r0.y; v2 += r1.x; v3 += r1.y;
            }
            *(float2*)&C[(size_t)row*DM_ + col]     = make_float2(v0, v1);
            *(float2*)&C[(size_t)(row+8)*DM_ + col] = make_float2(v2, v3);
        }
    }
}

// ---------------------------------------------------------------------------
// Flash attention, bf16 m16n8k16 mma (FA2-style register-resident P).
//  - K/V tiles stored bf16x2-packed, stride 36 uints (=4 mod 32: all LDSM
//    phases and qf loads conflict-free).
//  - QK^T B-frags: ldmatrix.x4 (K row-major);  PV B-frags: ldmatrix.x4.trans
//    (V row-major, HW transpose).  P: C-frag pairs packed to bf16 A-frags in
//    registers — no smem round-trip, 2 barriers/tile instead of 4.
// Block = 128 threads (4 warps), 64 q-rows, 64-key tiles. smem 18KB.
// ---------------------------------------------------------------------------
#define FST 36

__global__ __launch_bounds__(128)
void flash_tc(const int* __restrict__ mask)
{
    __shared__ unsigned Ks[64*FST];
    __shared__ unsigned Vs[64*FST];

    const int tid = threadIdx.x;
    const int warp = tid >> 5, lane = tid & 31;
    const int g = lane >> 2, t = lane & 3;
    const int q0 = blockIdx.x * 64;
    const int bh = blockIdx.y, b = bh >> 4, h = bh & 15;
    const int wq = warp * 16;
    const float scale = 0.125f;

    const unsigned Ks_sa = (unsigned)__cvta_generic_to_shared(Ks);
    const unsigned Vs_sa = (unsigned)__cvta_generic_to_shared(Vs);

    // Stage Q (scaled, bf16-packed) into Ks, extract A-frags, then Ks is K's.
    {
        const float* src = g_Q + ((size_t)(b*S_ + q0))*DM_ + h*HD_;
        #pragma unroll
        for (int i = 0; i < 8; i++) {
            int idx = tid + i*128;
            int r = idx >> 4, c4 = idx & 15;
            float4 v = *(const float4*)(src + (size_t)r*DM_ + c4*4);
            unsigned u0 = packbf(v.x*scale, v.y*scale);
            unsigned u1 = packbf(v.z*scale, v.w*scale);
            *(uint2*)&Ks[r*FST + c4*2] = make_uint2(u0, u1);
        }
    }
    __syncthreads();

    unsigned qf[4][4];
    #pragma unroll
    for (int ks = 0; ks < 4; ks++) {
        int base = (wq + g)*FST + ks*8 + t;
        qf[ks][0] = Ks[base];
        qf[ks][1] = Ks[base + 8*FST];
        qf[ks][2] = Ks[base + 4];
        qf[ks][3] = Ks[base + 8*FST + 4];
    }

    float o[8][4];
    #pragma unroll
    for (int nt = 0; nt < 8; nt++)
        #pragma unroll
        for (int i = 0; i < 4; i++) o[nt][i] = 0.f;
    float mi[2] = {-1e30f, -1e30f}, li[2] = {0.f, 0.f};

    const int* mrow0 = mask + ((size_t)b*S_ + q0 + wq + g)*S_;
    const int* mrow1 = mrow0 + 8*S_;

    // Per-lane ldmatrix base offsets (bytes).
    // K (non-trans): lanes 0-7 tile(keys nt16+0..7, d ks16), 8-15 (+d8),
    //                16-23 (keys +8), 24-31 (keys+8, d+8)
    const unsigned kaddr0 = Ks_sa +
        (((lane & 7) + ((lane >> 4) & 1)*8)*FST + ((lane >> 3) & 1)*4)*4u;
    // V (trans): lanes 0-7 tile(keys ks16+0..7, d nt16), 8-15 (keys +8),
    //            16-23 (d +8), 24-31 (keys+8, d+8)
    const unsigned vaddr0 = Vs_sa +
        (((lane & 7) + ((lane >> 3) & 1)*8)*FST + ((lane >> 4) & 1)*4)*4u;

    for (int k0 = 0; k0 < S_; k0 += 64) {
        __syncthreads();   // previous tile's LDSM reads done
        {
            const float* ksrc = g_K + ((size_t)(b*S_ + k0))*DM_ + h*HD_;
            const float* vsrc = g_V + ((size_t)(b*S_ + k0))*DM_ + h*HD_;
            #pragma unroll
            for (int i = 0; i < 8; i++) {
                int idx = tid + i*128;
                int r = idx >> 4, c4 = idx & 15;
                float4 kv = *(const float4*)(ksrc + (size_t)r*DM_ + c4*4);
                float4 vv = *(const float4*)(vsrc + (size_t)r*DM_ + c4*4);
                *(uint2*)&Ks[r*FST + c4*2] = make_uint2(packbf(kv.x, kv.y), packbf(kv.z, kv.w));
                *(uint2*)&Vs[r*FST + c4*2] = make_uint2(packbf(vv.x, vv.y), packbf(vv.z, vv.w));
            }
        }
        __syncthreads();

        // S = Q K^T   (4 k-steps of 16, 8 key-groups of 8)
        float s[8][4];
        #pragma unroll
        for (int nt = 0; nt < 8; nt++)
            #pragma unroll
            for (int i = 0; i < 4; i++) s[nt][i] = 0.f;

        #pragma unroll
        for (int ks = 0; ks < 4; ks++) {
            #pragma unroll
            for (int ntp = 0; ntp < 4; ntp++) {
                unsigned k0r, k1r, k2r, k3r;
                unsigned addr = kaddr0 + (unsigned)((ntp*16*FST + ks*8)*4);
                LDSM4(k0r, k1r, k2r, k3r, addr);
                mma16(s[2*ntp],   qf[ks], k0r, k1r);
                mma16(s[2*ntp+1], qf[ks], k2r, k3r);
            }
        }

        // Mask
        #pragma unroll
        for (int nt = 0; nt < 8; nt++) {
            int c = k0 + nt*8 + 2*t;
            int2 m0v = *(const int2*)&mrow0[c];
            int2 m1v = *(const int2*)&mrow1[c];
            if (m0v.x == 0) s[nt][0] = -1e9f;
            if (m0v.y == 0) s[nt][1] = -1e9f;
            if (m1v.x == 0) s[nt][2] = -1e9f;
            if (m1v.y == 0) s[nt][3] = -1e9f;
        }

        // Online softmax (rows g, g+8)
        #pragma unroll
        for (int rr = 0; rr < 2; rr++) {
            float mx = -1e30f;
            #pragma unroll
            for (int nt = 0; nt < 8; nt++)
                mx = fmaxf(mx, fmaxf(s[nt][2*rr], s[nt][2*rr+1]));
            mx = fmaxf(mx, __shfl_xor_sync(0xffffffffu, mx, 1));
            mx = fmaxf(mx, __shfl_xor_sync(0xffffffffu, mx, 2));
            float mnew = fmaxf(mi[rr], mx);
            float alpha = __expf(mi[rr] - mnew);
            float sum = 0.f;
            #pragma unroll
            for (int nt = 0; nt < 8; nt++) {
                s[nt][2*rr]   = __expf(s[nt][2*rr]   - mnew);
                s[nt][2*rr+1] = __expf(s[nt][2*rr+1] - mnew);
                sum += s[nt][2*rr] + s[nt][2*rr+1];
            }
            sum += __shfl_xor_sync(0xffffffffu, sum, 1);
            sum += __shfl_xor_sync(0xffffffffu, sum, 2);
            li[rr] = li[rr]*alpha + sum;
            mi[rr] = mnew;
            #pragma unroll
            for (int nt = 0; nt < 8; nt++) {
                o[nt][2*rr]   *= alpha;
                o[nt][2*rr+1] *= alpha;
            }
        }

        // O += P V : P packed from C-frags in registers (no smem round-trip).
        #pragma unroll
        for (int ks = 0; ks < 4; ks++) {
            unsigned pa[4];
            pa[0] = packbf(s[2*ks][0],   s[2*ks][1]);    // P[g][ks16+2t,+1]
            pa[1] = packbf(s[2*ks][2],   s[2*ks][3]);    // P[g+8][..]
            pa[2] = packbf(s[2*ks+1][0], s[2*ks+1][1]);  // P[g][ks16+8+2t,+1]
            pa[3] = packbf(s[2*ks+1][2], s[2*ks+1][3]);  // P[g+8][..]
            #pragma unroll
            for (int ntp = 0; ntp < 4; ntp++) {
                unsigned v0r, v1r, v2r, v3r;
                unsigned addr = vaddr0 + (unsigned)((ks*16*FST + ntp*8)*4);
                LDSM4T(v0r, v1r, v2r, v3r, addr);
                mma16(o[2*ntp],   pa, v0r, v1r);
                mma16(o[2*ntp+1], pa, v2r, v3r);
            }
        }
    }

    // Epilogue
    float inv0 = 1.f / li[0], inv1 = 1.f / li[1];
    float* dst0 = g_attn + ((size_t)(b*S_ + q0 + wq + g))*DM_ + h*HD_;
    float* dst1 = dst0 + (size_t)8*DM_;
    #pragma unroll
    for (int nt = 0; nt < 8; nt++) {
        int c = nt*8 + 2*t;
        *(float2*)&dst0[c] = make_float2(o[nt][0]*inv0, o[nt][1]*inv0);
        *(float2*)&dst1[c] = make_float2(o[nt][2]*inv1, o[nt][3]*inv1);
    }
}

// ---------------------------------------------------------------------------
// LayerNorm: unbiased std (ddof=1), denominator (std + eps). One block per row.
// ---------------------------------------------------------------------------
__global__ __launch_bounds__(256)
void layernorm(const float* __restrict__ gamma, const float* __restrict__ beta,
               float* __restrict__ out)
{
    __shared__ float red[2][8];
    const int row = blockIdx.x;
    const int tid = threadIdx.x;
    const float* xr = g_x + (size_t)row * DM_;
    const int c = tid * 4;

    float4 xv = *(const float4*)(xr + c);
    float sum = xv.x + xv.y + xv.z + xv.w;
    float sq  = xv.x*xv.x + xv.y*xv.y + xv.z*xv.z + xv.w*xv.w;

    #pragma unroll
    for (int off = 16; off > 0; off >>= 1) {
        sum += __shfl_xor_sync(0xffffffffu, sum, off);
        sq  += __shfl_xor_sync(0xffffffffu, sq,  off);
    }
    const int w = tid >> 5, lane = tid & 31;
    if (lane == 0) { red[0][w] = sum; red[1][w] = sq; }
    __syncthreads();
    if (tid == 0) {
        float s = 0.f, q = 0.f;
        #pragma unroll
        for (int i = 0; i < 8; i++) { s += red[0][i]; q += red[1][i]; }
        red[0][0] = s; red[1][0] = q;
    }
    __syncthreads();
    sum = red[0][0]; sq = red[1][0];

    float mean = sum / (float)DM_;
    float var  = (sq - (float)DM_ * mean * mean) / (float)(DM_ - 1);
    var = fmaxf(var, 0.f);
    float inv = 1.f / (sqrtf(var) + 1e-6f);

    float4 g4 = *(const float4*)(gamma + c);
    float4 b4 = *(const float4*)(beta + c);
    float4 ov;
    ov.x = g4.x * (xv.x - mean) * inv + b4.x;
    ov.y = g4.y * (xv.y - mean) * inv + b4.y;
    ov.z = g4.z * (xv.z - mean) * inv + b4.z;
    ov.w = g4.w * (xv.w - mean) * inv + b4.w;
    *(float4*)(out + (size_t)row * DM_ + c) = ov;
}

// ---------------------------------------------------------------------------
extern "C" void kernel_launch(void* const* d_in, const int* in_sizes, int n_in,
                              void* d_out, int out_size)
{
    (void)in_sizes; (void)n_in; (void)out_size;
    const float* query = (const float*)d_in[0];
    const float* key_  = (const float*)d_in[1];
    const float* value = (const float*)d_in[2];
    const int*   mask  = (const int*)  d_in[3];
    const float* Wq = (const float*)d_in[4];
    const float* bq = (const float*)d_in[5];
    const float* Wk = (const float*)d_in[6];
    const float* bk = (const float*)d_in[7];
    const float* Wv = (const float*)d_in[8];
    const float* bv = (const float*)d_in[9];
    const float* Wo = (const float*)d_in[10];
    const float* bo = (const float*)d_in[11];
    const float* gamma = (const float*)d_in[12];
    const float* beta  = (const float*)d_in[13];
    float* out = (float*)d_out;

    dim3 gg(DM_/128, MTOT/128);   // (8, 32)
    tgemm<false><<<gg, 256>>>(query, Wq, bq, nullptr, 0);
    tgemm<false><<<gg, 256>>>(key_,  Wk, bk, nullptr, 1);
    tgemm<false><<<gg, 256>>>(value, Wv, bv, nullptr, 2);

    flash_tc<<<dim3(S_/64, B_*H_), 128>>>(mask);

    tgemm<true><<<gg, 256>>>(nullptr, Wo, bo, query, 3);

    layernorm<<<MTOT, 256>>>(gamma, beta, out);
}